// round 1
// baseline (speedup 1.0000x reference)
#include <cuda_runtime.h>

#define BATCH 16
#define NQ    16384
#define CH    64
#define NKV   256
#define EPS   1e-5f

// Scratch (device globals — no allocation allowed)
__device__ float g_xconv[BATCH * NKV * CH];   // conv output   [b*256+pos][c]
__device__ float g_G[BATCH * CH * NKV];       // scale*Wq@K^T  [b][d][j]
__device__ float g_VW[BATCH * NKV * CH];      // V@Wo          [b][j][c]
__device__ float g_sbias[BATCH * NKV];        // scale*(bq . k_j)

// ---------------------------------------------------------------------------
// Kernel A: strided conv as GEMM  xconv[4096,64] = A[4096,4096] @ convw[4096,64] + convb
// A row = one 8x8x64 patch (k-chunk of 64 == one (di,dj) position, contiguous in c)
// 128 blocks x 32 rows, 128 threads, 4x4 register tiles.
// ---------------------------------------------------------------------------
__global__ void __launch_bounds__(128, 1) conv_kernel(
    const float* __restrict__ inp,
    const float* __restrict__ convw,
    const float* __restrict__ convb)
{
    __shared__ float sA[32 * 68];   // padded: 4-row stride 272 -> bank offset 16
    __shared__ float sB[64 * 64];

    int t  = threadIdx.x;
    int r0 = 4 * (t >> 4);
    int c0 = 4 * (t & 15);

    float acc[4][4] = {};

    // precompute per-thread A-load row bases
    int rarr[4], kkarr[4], rowbase[4];
#pragma unroll
    for (int it = 0; it < 4; ++it) {
        int f4i = it * 128 + t;
        int r   = f4i >> 4;
        int kk  = (f4i & 15) * 4;
        int rg  = blockIdx.x * 32 + r;          // global row = b*256 + patch
        int b   = rg >> 8;
        int patch = rg & 255;
        int pi  = patch >> 4, pj = patch & 15;
        rarr[it]  = r;
        kkarr[it] = kk;
        rowbase[it] = (b << 14) + (pi << 10) + (pj << 3);  // b*16384 + pi*8*128 + pj*8
    }

    for (int kc = 0; kc < 64; ++kc) {
        int di = kc >> 3, dj = kc & 7;
#pragma unroll
        for (int it = 0; it < 4; ++it) {
            const float4 v = *(const float4*)&inp[((rowbase[it] + di * 128 + dj) << 6) + kkarr[it]];
            *(float4*)&sA[rarr[it] * 68 + kkarr[it]] = v;
        }
#pragma unroll
        for (int it = 0; it < 8; ++it) {
            int f4i = it * 128 + t;
            *(float4*)&sB[f4i * 4] = *(const float4*)&convw[(kc << 12) + f4i * 4];
        }
        __syncthreads();

#pragma unroll 16
        for (int k = 0; k < 64; ++k) {
            float4 bv = *(const float4*)&sB[k * 64 + c0];
#pragma unroll
            for (int ri = 0; ri < 4; ++ri) {
                float av = sA[(r0 + ri) * 68 + k];
                acc[ri][0] += av * bv.x;
                acc[ri][1] += av * bv.y;
                acc[ri][2] += av * bv.z;
                acc[ri][3] += av * bv.w;
            }
        }
        __syncthreads();
    }

    float4 cb = *(const float4*)&convb[c0];
#pragma unroll
    for (int ri = 0; ri < 4; ++ri) {
        int rg = blockIdx.x * 32 + r0 + ri;
        float4 o = make_float4(acc[ri][0] + cb.x, acc[ri][1] + cb.y,
                               acc[ri][2] + cb.z, acc[ri][3] + cb.w);
        *(float4*)&g_xconv[rg * 64 + c0] = o;
    }
}

// ---------------------------------------------------------------------------
// Kernel B: per kv position — LayerNorm, kv = xn@Wkv+bkv, then
//   G[b][d][pos]   = 0.125 * dot(Wq[d,:], k)
//   VW[b][pos][c]  = dot(v, Wo[:,c])
//   sbias[b][pos]  = 0.125 * dot(bq, k)
// 512 blocks x 8 positions, 256 threads. Weights staged in smem (dynamic).
// ---------------------------------------------------------------------------
__global__ void __launch_bounds__(256, 1) kv_kernel(
    const float* __restrict__ Wq,  const float* __restrict__ bq,
    const float* __restrict__ Wkv, const float* __restrict__ bkv,
    const float* __restrict__ Wo,
    const float* __restrict__ gamma, const float* __restrict__ beta)
{
    extern __shared__ float sm[];
    float* sWkv = sm;            // 8192
    float* sWo  = sm + 8192;     // 4096
    float* sWqT = sm + 12288;    // 64*65 = 4160 (transposed, padded)
    float* sx   = sm + 16448;    // 64
    float* sxn  = sm + 16512;    // 64
    float* skv  = sm + 16576;    // 128
    float* sgam = sm + 16704;    // 64
    float* sbet = sm + 16768;    // 64
    float* sbq  = sm + 16832;    // 64
    float* sbkv = sm + 16896;    // 128
    float* sstat= sm + 17024;    // 2

    int t = threadIdx.x;

#pragma unroll
    for (int it = 0; it < 8; ++it)
        ((float4*)sWkv)[it * 256 + t] = ((const float4*)Wkv)[it * 256 + t];
#pragma unroll
    for (int it = 0; it < 4; ++it)
        ((float4*)sWo)[it * 256 + t] = ((const float4*)Wo)[it * 256 + t];
#pragma unroll
    for (int it = 0; it < 4; ++it) {
        int f4i = it * 256 + t;
        int d = f4i >> 4, cc = (f4i & 15) * 4;
        float4 v = ((const float4*)Wq)[f4i];
        sWqT[(cc + 0) * 65 + d] = v.x;
        sWqT[(cc + 1) * 65 + d] = v.y;
        sWqT[(cc + 2) * 65 + d] = v.z;
        sWqT[(cc + 3) * 65 + d] = v.w;
    }
    if (t < 64)  { sgam[t] = gamma[t]; sbet[t] = beta[t]; sbq[t] = bq[t]; }
    if (t < 128) { sbkv[t] = bkv[t]; }
    __syncthreads();

    for (int p = 0; p < 8; ++p) {
        int j = blockIdx.x * 8 + p;
        if (t < 64) sx[t] = g_xconv[j * 64 + t];
        __syncthreads();

        if (t < 32) {
            float a = sx[t], b2 = sx[t + 32];
            float s = a + b2;
            float q = a * a + b2 * b2;
#pragma unroll
            for (int off = 16; off > 0; off >>= 1) {
                s += __shfl_xor_sync(0xffffffffu, s, off);
                q += __shfl_xor_sync(0xffffffffu, q, off);
            }
            if (t == 0) {
                float mean = s * (1.0f / 64.0f);
                sstat[0] = mean;
                sstat[1] = rsqrtf(q * (1.0f / 64.0f) - mean * mean + EPS);
            }
        }
        __syncthreads();
        if (t < 64)
            sxn[t] = (sx[t] - sstat[0]) * sstat[1] * sgam[t] + sbet[t];
        __syncthreads();

        if (t < 128) {
            float a = sbkv[t];
#pragma unroll 16
            for (int c = 0; c < 64; ++c)
                a += sxn[c] * sWkv[c * 128 + t];
            skv[t] = a;
        }
        __syncthreads();

        int b = j >> 8, pos = j & 255;
        if (t < 64) {
            float a = 0.0f;
#pragma unroll 16
            for (int c = 0; c < 64; ++c)
                a += sWqT[c * 65 + t] * skv[c];
            g_G[(b << 14) + t * 256 + pos] = 0.125f * a;
        } else if (t < 128) {
            int cc = t - 64;
            float a = 0.0f;
#pragma unroll 16
            for (int d = 0; d < 64; ++d)
                a += skv[64 + d] * sWo[d * 64 + cc];
            g_VW[(b << 14) + pos * 64 + cc] = a;
        } else if (t == 128) {
            float a = 0.0f;
            for (int c = 0; c < 64; ++c)
                a += sbq[c] * skv[c];
            g_sbias[(b << 8) + pos] = 0.125f * a;
        }
        __syncthreads();
    }
}

// ---------------------------------------------------------------------------
// Kernel C: fused attention per (batch, 64-query tile)
//   S[64,256] = X[64,64] @ G[64,256] + sbias    (pre-scaled)
//   row softmax (1/sum deferred to epilogue)
//   out = P @ VW * rinv + bo
// 256 threads, 210 KB dynamic smem (1 block/SM).
// ---------------------------------------------------------------------------
__global__ void __launch_bounds__(256, 1) attn_kernel(
    const float* __restrict__ inp,
    const float* __restrict__ bo,
    float* __restrict__ out)
{
    extern __shared__ float sm[];
    float* sG    = sm;            // 16384
    float* sVW   = sm + 16384;    // 16384
    float* sS    = sm + 32768;    // 64*260 = 16640 (padded rows: stride%32 == 4)
    float* sX    = sm + 49408;    // 4096
    float* sbs   = sm + 53504;    // 256
    float* sbo   = sm + 53760;    // 64
    float* srinv = sm + 53824;    // 64

    int t  = threadIdx.x;
    int b  = blockIdx.y;
    int n0 = blockIdx.x * 64;

    // ---- loads ----
    {
        const float4* gG = (const float4*)(g_G + (b << 14));
        const float4* gV = (const float4*)(g_VW + (b << 14));
#pragma unroll
        for (int it = 0; it < 16; ++it) {
            ((float4*)sG)[it * 256 + t]  = gG[it * 256 + t];
            ((float4*)sVW)[it * 256 + t] = gV[it * 256 + t];
        }
        const float4* gX = (const float4*)(inp + (((size_t)(b << 14) + n0) << 6));
#pragma unroll
        for (int it = 0; it < 4; ++it)
            ((float4*)sX)[it * 256 + t] = gX[it * 256 + t];
        if (t < 64) ((float4*)sbs)[t] = ((const float4*)(g_sbias + (b << 8)))[t];
        if (t < 16) ((float4*)sbo)[t] = ((const float4*)bo)[t];
    }
    __syncthreads();

    // ---- Phase 1: S = X @ G + sbias  (8x8 register tile per thread) ----
    {
        int i0 = (t >> 5) * 8;        // whole warp shares i0 -> X reads broadcast
        int ja = (t & 31) * 4;        // contiguous across lanes -> conflict-free
        int jb = 128 + ja;
        float acc[8][8] = {};

#pragma unroll 2
        for (int d = 0; d < 64; ++d) {
            float4 ga = *(const float4*)&sG[d * 256 + ja];
            float4 gb = *(const float4*)&sG[d * 256 + jb];
#pragma unroll
            for (int r = 0; r < 8; ++r) {
                float xv = sX[(i0 + r) * 64 + d];
                acc[r][0] += xv * ga.x; acc[r][1] += xv * ga.y;
                acc[r][2] += xv * ga.z; acc[r][3] += xv * ga.w;
                acc[r][4] += xv * gb.x; acc[r][5] += xv * gb.y;
                acc[r][6] += xv * gb.z; acc[r][7] += xv * gb.w;
            }
        }
        float4 ba = *(const float4*)&sbs[ja];
        float4 bb = *(const float4*)&sbs[jb];
#pragma unroll
        for (int r = 0; r < 8; ++r) {
            int row = i0 + r;
            float4 o1 = make_float4(acc[r][0] + ba.x, acc[r][1] + ba.y,
                                    acc[r][2] + ba.z, acc[r][3] + ba.w);
            float4 o2 = make_float4(acc[r][4] + bb.x, acc[r][5] + bb.y,
                                    acc[r][6] + bb.z, acc[r][7] + bb.w);
            *(float4*)&sS[row * 260 + ja] = o1;
            *(float4*)&sS[row * 260 + jb] = o2;
        }
    }
    __syncthreads();

    // ---- Phase 2: row softmax (store exp, defer 1/sum) ----
    if (t < 64) {
        float* row = sS + t * 260;
        float m = -1e30f;
#pragma unroll 8
        for (int jj = 0; jj < 64; ++jj) {
            float4 v = *(const float4*)&row[jj * 4];
            m = fmaxf(m, fmaxf(fmaxf(v.x, v.y), fmaxf(v.z, v.w)));
        }
        float s = 0.0f;
#pragma unroll 8
        for (int jj = 0; jj < 64; ++jj) {
            float4 v = *(const float4*)&row[jj * 4];
            v.x = __expf(v.x - m); v.y = __expf(v.y - m);
            v.z = __expf(v.z - m); v.w = __expf(v.w - m);
            s += v.x + v.y + v.z + v.w;
            *(float4*)&row[jj * 4] = v;
        }
        srinv[t] = 1.0f / s;
    }
    __syncthreads();

    // ---- Phase 3: out = P @ VW * rinv + bo  (4x4 tile per thread) ----
    {
        int i0 = (t >> 4) * 4;
        int c0 = (t & 15) * 4;
        float a2[4][4] = {};
#pragma unroll 4
        for (int j = 0; j < 256; ++j) {
            float4 vv = *(const float4*)&sVW[j * 64 + c0];
#pragma unroll
            for (int r = 0; r < 4; ++r) {
                float p = sS[(i0 + r) * 260 + j];
                a2[r][0] += p * vv.x; a2[r][1] += p * vv.y;
                a2[r][2] += p * vv.z; a2[r][3] += p * vv.w;
            }
        }
        float4 bov = *(const float4*)&sbo[c0];
#pragma unroll
        for (int r = 0; r < 4; ++r) {
            int row = i0 + r;
            float rv = srinv[row];
            float4 o = make_float4(a2[r][0] * rv + bov.x, a2[r][1] * rv + bov.y,
                                   a2[r][2] * rv + bov.z, a2[r][3] * rv + bov.w);
            *(float4*)&out[(((size_t)(b << 14) + n0 + row) << 6) + c0] = o;
        }
    }
}

// ---------------------------------------------------------------------------
extern "C" void kernel_launch(void* const* d_in, const int* in_sizes, int n_in,
                              void* d_out, int out_size)
{
    const float* inp   = (const float*)d_in[0];
    const float* Wq    = (const float*)d_in[1];
    const float* bq    = (const float*)d_in[2];
    const float* Wkv   = (const float*)d_in[3];
    const float* bkv   = (const float*)d_in[4];
    const float* Wo    = (const float*)d_in[5];
    const float* bo    = (const float*)d_in[6];
    const float* convw = (const float*)d_in[7];
    const float* convb = (const float*)d_in[8];
    const float* gamma = (const float*)d_in[9];
    const float* beta  = (const float*)d_in[10];
    float* out = (float*)d_out;

    const int smemB = 17026 * 4;   // 68104 B
    const int smemC = 53888 * 4;   // 215552 B
    cudaFuncSetAttribute(kv_kernel,   cudaFuncAttributeMaxDynamicSharedMemorySize, smemB);
    cudaFuncSetAttribute(attn_kernel, cudaFuncAttributeMaxDynamicSharedMemorySize, smemC);

    conv_kernel<<<128, 128>>>(inp, convw, convb);
    kv_kernel<<<512, 256, smemB>>>(Wq, bq, Wkv, bkv, Wo, gamma, beta);
    attn_kernel<<<dim3(256, 16), 256, smemC>>>(inp, bo, out);
}

// round 2
// speedup vs baseline: 1.0486x; 1.0486x over previous
#include <cuda_runtime.h>

#define BATCH 16
#define NQ    16384
#define CH    64
#define NKV   256
#define EPS   1e-5f

typedef unsigned long long ull;

// Scratch (device globals — no allocation allowed)
__device__ float g_xconv[BATCH * NKV * CH];   // conv output   [b*256+pos][c]
__device__ float g_G[BATCH * CH * NKV];       // scale*Wq@K^T  [b][d][j]
__device__ float g_VW[BATCH * NKV * CH];      // V@Wo          [b][j][c]
__device__ float g_sbias[BATCH * NKV];        // scale*(bq . k_j)

// ---- packed fp32x2 helpers ------------------------------------------------
__device__ __forceinline__ void fma2(ull& d, ull a, ull b) {
    asm("fma.rn.f32x2 %0, %1, %2, %0;" : "+l"(d) : "l"(a), "l"(b));
}
__device__ __forceinline__ ull add2(ull a, ull b) {
    ull r; asm("add.rn.f32x2 %0, %1, %2;" : "=l"(r) : "l"(a), "l"(b)); return r;
}
__device__ __forceinline__ ull pack2(float lo, float hi) {
    ull r; asm("mov.b64 %0, {%1, %2};" : "=l"(r) : "f"(lo), "f"(hi)); return r;
}
__device__ __forceinline__ float2 unpack2(ull v) {
    float2 r; asm("mov.b64 {%0, %1}, %2;" : "=f"(r.x), "=f"(r.y) : "l"(v)); return r;
}

// ---------------------------------------------------------------------------
// Kernel A: strided conv as GEMM  xconv[4096,64] = A[4096,4096] @ convw[4096,64] + convb
// 256 blocks x 16 rows, 128 threads, 2x4 thread tiles, f32x2 packed over cols.
// 2 blocks/SM resident.
// ---------------------------------------------------------------------------
__global__ void __launch_bounds__(128, 2) conv_kernel(
    const float* __restrict__ inp,
    const float* __restrict__ convw,
    const float* __restrict__ convb)
{
    __shared__ float sA[16 * 68];
    __shared__ float sB[64 * 64];

    int t  = threadIdx.x;
    int r0 = (t >> 4) * 2;       // 8 rowgroups x 2 rows = 16
    int c0 = (t & 15) * 4;       // 16 colgroups x 4 cols = 64

    ull acc[2][2] = {{0ull, 0ull}, {0ull, 0ull}};

    // per-thread A-load addressing (2 float4 per chunk)
    int rarr[2], kkarr[2], rowbase[2];
#pragma unroll
    for (int it = 0; it < 2; ++it) {
        int f4i = it * 128 + t;
        int r   = f4i >> 4;
        int kk  = (f4i & 15) * 4;
        int rg  = blockIdx.x * 16 + r;          // global row = b*256 + patch
        int b   = rg >> 8;
        int patch = rg & 255;
        int pi  = patch >> 4, pj = patch & 15;
        rarr[it]  = r;
        kkarr[it] = kk;
        rowbase[it] = (b << 14) + (pi << 10) + (pj << 3);
    }

    for (int kc = 0; kc < 64; ++kc) {
        int di = kc >> 3, dj = kc & 7;
#pragma unroll
        for (int it = 0; it < 2; ++it) {
            const float4 v = *(const float4*)&inp[((rowbase[it] + di * 128 + dj) << 6) + kkarr[it]];
            *(float4*)&sA[rarr[it] * 68 + kkarr[it]] = v;
        }
#pragma unroll
        for (int it = 0; it < 8; ++it) {
            int f4i = it * 128 + t;
            *(float4*)&sB[f4i * 4] = *(const float4*)&convw[(kc << 12) + f4i * 4];
        }
        __syncthreads();

#pragma unroll 16
        for (int k = 0; k < 64; ++k) {
            float a0 = sA[r0 * 68 + k];
            float a1 = sA[(r0 + 1) * 68 + k];
            ull d0 = pack2(a0, a0);
            ull d1 = pack2(a1, a1);
            ulonglong2 bv = *(const ulonglong2*)&sB[k * 64 + c0];
            fma2(acc[0][0], d0, bv.x);
            fma2(acc[0][1], d0, bv.y);
            fma2(acc[1][0], d1, bv.x);
            fma2(acc[1][1], d1, bv.y);
        }
        __syncthreads();
    }

    float4 cb = *(const float4*)&convb[c0];
    ull cb01 = pack2(cb.x, cb.y), cb23 = pack2(cb.z, cb.w);
#pragma unroll
    for (int ri = 0; ri < 2; ++ri) {
        int rg = blockIdx.x * 16 + r0 + ri;
        ulonglong2 o;
        o.x = add2(acc[ri][0], cb01);
        o.y = add2(acc[ri][1], cb23);
        *(ulonglong2*)&g_xconv[rg * 64 + c0] = o;
    }
}

// ---------------------------------------------------------------------------
// Kernel B: per kv position — LayerNorm, kv = xn@Wkv+bkv, then
//   G[b][d][pos]   = 0.125 * dot(Wq[d,:], k)
//   VW[b][pos][c]  = dot(v, Wo[:,c])
//   sbias[b][pos]  = 0.125 * dot(bq, k)
// ---------------------------------------------------------------------------
__global__ void __launch_bounds__(256, 1) kv_kernel(
    const float* __restrict__ Wq,  const float* __restrict__ bq,
    const float* __restrict__ Wkv, const float* __restrict__ bkv,
    const float* __restrict__ Wo,
    const float* __restrict__ gamma, const float* __restrict__ beta)
{
    extern __shared__ float sm[];
    float* sWkv = sm;            // 8192
    float* sWo  = sm + 8192;     // 4096
    float* sWqT = sm + 12288;    // 64*65 = 4160 (transposed, padded)
    float* sx   = sm + 16448;    // 64
    float* sxn  = sm + 16512;    // 64
    float* skv  = sm + 16576;    // 128
    float* sgam = sm + 16704;    // 64
    float* sbet = sm + 16768;    // 64
    float* sbq  = sm + 16832;    // 64
    float* sbkv = sm + 16896;    // 128
    float* sstat= sm + 17024;    // 2

    int t = threadIdx.x;

#pragma unroll
    for (int it = 0; it < 8; ++it)
        ((float4*)sWkv)[it * 256 + t] = ((const float4*)Wkv)[it * 256 + t];
#pragma unroll
    for (int it = 0; it < 4; ++it)
        ((float4*)sWo)[it * 256 + t] = ((const float4*)Wo)[it * 256 + t];
#pragma unroll
    for (int it = 0; it < 4; ++it) {
        int f4i = it * 256 + t;
        int d = f4i >> 4, cc = (f4i & 15) * 4;
        float4 v = ((const float4*)Wq)[f4i];
        sWqT[(cc + 0) * 65 + d] = v.x;
        sWqT[(cc + 1) * 65 + d] = v.y;
        sWqT[(cc + 2) * 65 + d] = v.z;
        sWqT[(cc + 3) * 65 + d] = v.w;
    }
    if (t < 64)  { sgam[t] = gamma[t]; sbet[t] = beta[t]; sbq[t] = bq[t]; }
    if (t < 128) { sbkv[t] = bkv[t]; }
    __syncthreads();

    for (int p = 0; p < 8; ++p) {
        int j = blockIdx.x * 8 + p;
        if (t < 64) sx[t] = g_xconv[j * 64 + t];
        __syncthreads();

        if (t < 32) {
            float a = sx[t], b2 = sx[t + 32];
            float s = a + b2;
            float q = a * a + b2 * b2;
#pragma unroll
            for (int off = 16; off > 0; off >>= 1) {
                s += __shfl_xor_sync(0xffffffffu, s, off);
                q += __shfl_xor_sync(0xffffffffu, q, off);
            }
            if (t == 0) {
                float mean = s * (1.0f / 64.0f);
                sstat[0] = mean;
                sstat[1] = rsqrtf(q * (1.0f / 64.0f) - mean * mean + EPS);
            }
        }
        __syncthreads();
        if (t < 64)
            sxn[t] = (sx[t] - sstat[0]) * sstat[1] * sgam[t] + sbet[t];
        __syncthreads();

        if (t < 128) {
            float a = sbkv[t];
#pragma unroll 16
            for (int c = 0; c < 64; ++c)
                a += sxn[c] * sWkv[c * 128 + t];
            skv[t] = a;
        }
        __syncthreads();

        int b = j >> 8, pos = j & 255;
        if (t < 64) {
            float a = 0.0f;
#pragma unroll 16
            for (int c = 0; c < 64; ++c)
                a += sWqT[c * 65 + t] * skv[c];
            g_G[(b << 14) + t * 256 + pos] = 0.125f * a;
        } else if (t < 128) {
            int cc = t - 64;
            float a = 0.0f;
#pragma unroll 16
            for (int d = 0; d < 64; ++d)
                a += skv[64 + d] * sWo[d * 64 + cc];
            g_VW[(b << 14) + pos * 64 + cc] = a;
        } else if (t == 128) {
            float a = 0.0f;
            for (int c = 0; c < 64; ++c)
                a += sbq[c] * skv[c];
            g_sbias[(b << 8) + pos] = 0.125f * a;
        }
        __syncthreads();
    }
}

// ---------------------------------------------------------------------------
// Kernel C: fused attention per (batch, 64-query tile), fp32x2 packed.
//   S^T[256,64] = (X[64,64] @ G[64,256] + sbias)^T   (packed over row pairs)
//   row softmax (exp in-place, 1/sum deferred; 4 lanes per row)
//   out = P @ VW * rinv + bo                          (packed over row pairs)
// 256 threads, ~217 KB dynamic smem, 1 block/SM.
// ---------------------------------------------------------------------------
__global__ void __launch_bounds__(256, 1) attn_kernel(
    const float* __restrict__ inp,
    const float* __restrict__ bo,
    float* __restrict__ out)
{
    extern __shared__ float sm[];
    float* sG    = sm;            // 16384     [d][j]      (64 x 256)
    float* sVW   = sm + 16384;    // 16384     [j][c]      (256 x 64)
    float* sST   = sm + 32768;    // 256*66 = 16896  S^T: [j][row], stride 66
    float* sXT   = sm + 49664;    // 64*66  = 4224   X^T: [d][row], stride 66
    float* sbs   = sm + 53888;    // 256
    float* sbo   = sm + 54144;    // 64
    float* srinv = sm + 54208;    // 64

    int t  = threadIdx.x;
    int b  = blockIdx.y;
    int n0 = blockIdx.x * 64;

    // ---- loads ----
    {
        const float4* gG = (const float4*)(g_G + (b << 14));
        const float4* gV = (const float4*)(g_VW + (b << 14));
#pragma unroll
        for (int it = 0; it < 16; ++it) {
            ((float4*)sG)[it * 256 + t]  = gG[it * 256 + t];
            ((float4*)sVW)[it * 256 + t] = gV[it * 256 + t];
        }
        const float4* gX = (const float4*)(inp + (((size_t)(b << 14) + n0) << 6));
#pragma unroll
        for (int it = 0; it < 4; ++it) {
            int f4i = it * 256 + t;
            int row = f4i >> 4, dd = (f4i & 15) * 4;
            float4 v = gX[f4i];
            sXT[(dd + 0) * 66 + row] = v.x;
            sXT[(dd + 1) * 66 + row] = v.y;
            sXT[(dd + 2) * 66 + row] = v.z;
            sXT[(dd + 3) * 66 + row] = v.w;
        }
        if (t < 64) ((float4*)sbs)[t] = ((const float4*)(g_sbias + (b << 8)))[t];
        if (t < 16) ((float4*)sbo)[t] = ((const float4*)bo)[t];
    }
    __syncthreads();

    // ---- Phase 1: S^T = (X @ G + sbias)^T, packed over query-row pairs ----
    {
        int i0 = (t >> 5) * 8;        // warp-uniform -> x reads broadcast
        int ja = (t & 31) * 4;        // conflict-free G reads
        int jb = 128 + ja;
        ull acc2[4][8];
#pragma unroll
        for (int rp = 0; rp < 4; ++rp)
#pragma unroll
            for (int c = 0; c < 8; ++c) acc2[rp][c] = 0ull;

#pragma unroll 4
        for (int d = 0; d < 64; ++d) {
            const float* xt = &sXT[d * 66 + i0];
            ull x0 = *(const ull*)&xt[0];
            ull x1 = *(const ull*)&xt[2];
            ull x2 = *(const ull*)&xt[4];
            ull x3 = *(const ull*)&xt[6];
            float4 ga = *(const float4*)&sG[d * 256 + ja];
            float4 gb = *(const float4*)&sG[d * 256 + jb];
            ull g0 = pack2(ga.x, ga.x), g1 = pack2(ga.y, ga.y);
            ull g2 = pack2(ga.z, ga.z), g3 = pack2(ga.w, ga.w);
            ull g4 = pack2(gb.x, gb.x), g5 = pack2(gb.y, gb.y);
            ull g6 = pack2(gb.z, gb.z), g7 = pack2(gb.w, gb.w);
            fma2(acc2[0][0], x0, g0); fma2(acc2[0][1], x0, g1);
            fma2(acc2[0][2], x0, g2); fma2(acc2[0][3], x0, g3);
            fma2(acc2[0][4], x0, g4); fma2(acc2[0][5], x0, g5);
            fma2(acc2[0][6], x0, g6); fma2(acc2[0][7], x0, g7);
            fma2(acc2[1][0], x1, g0); fma2(acc2[1][1], x1, g1);
            fma2(acc2[1][2], x1, g2); fma2(acc2[1][3], x1, g3);
            fma2(acc2[1][4], x1, g4); fma2(acc2[1][5], x1, g5);
            fma2(acc2[1][6], x1, g6); fma2(acc2[1][7], x1, g7);
            fma2(acc2[2][0], x2, g0); fma2(acc2[2][1], x2, g1);
            fma2(acc2[2][2], x2, g2); fma2(acc2[2][3], x2, g3);
            fma2(acc2[2][4], x2, g4); fma2(acc2[2][5], x2, g5);
            fma2(acc2[2][6], x2, g6); fma2(acc2[2][7], x2, g7);
            fma2(acc2[3][0], x3, g0); fma2(acc2[3][1], x3, g1);
            fma2(acc2[3][2], x3, g2); fma2(acc2[3][3], x3, g3);
            fma2(acc2[3][4], x3, g4); fma2(acc2[3][5], x3, g5);
            fma2(acc2[3][6], x3, g6); fma2(acc2[3][7], x3, g7);
        }

        float4 ba = *(const float4*)&sbs[ja];
        float4 bb = *(const float4*)&sbs[jb];
        ull bd[8] = { pack2(ba.x, ba.x), pack2(ba.y, ba.y),
                      pack2(ba.z, ba.z), pack2(ba.w, ba.w),
                      pack2(bb.x, bb.x), pack2(bb.y, bb.y),
                      pack2(bb.z, bb.z), pack2(bb.w, bb.w) };
#pragma unroll
        for (int rp = 0; rp < 4; ++rp) {
#pragma unroll
            for (int c = 0; c < 8; ++c) {
                int col = (c < 4) ? (ja + c) : (jb + c - 4);
                *(ull*)&sST[col * 66 + i0 + 2 * rp] = add2(acc2[rp][c], bd[c]);
            }
        }
    }
    __syncthreads();

    // ---- Phase 2: softmax over j, 4 lanes per row, exp in place ----
    {
        int r = t >> 2, q = t & 3;
        float m = -1e30f;
#pragma unroll 16
        for (int jj = 0; jj < 64; ++jj)
            m = fmaxf(m, sST[(q * 64 + jj) * 66 + r]);
        m = fmaxf(m, __shfl_xor_sync(0xffffffffu, m, 1));
        m = fmaxf(m, __shfl_xor_sync(0xffffffffu, m, 2));
        float s = 0.0f;
#pragma unroll 16
        for (int jj = 0; jj < 64; ++jj) {
            int idx = (q * 64 + jj) * 66 + r;
            float e = __expf(sST[idx] - m);
            s += e;
            sST[idx] = e;
        }
        s += __shfl_xor_sync(0xffffffffu, s, 1);
        s += __shfl_xor_sync(0xffffffffu, s, 2);
        if (q == 0) srinv[r] = 1.0f / s;
    }
    __syncthreads();

    // ---- Phase 3: out = P @ VW * rinv + bo, packed over row pairs ----
    {
        int i0 = (t >> 4) * 4;
        int c0 = (t & 15) * 4;
        ull acc3[2][4];
#pragma unroll
        for (int rp = 0; rp < 2; ++rp)
#pragma unroll
            for (int c = 0; c < 4; ++c) acc3[rp][c] = 0ull;

#pragma unroll 4
        for (int j = 0; j < 256; ++j) {
            ull p0 = *(const ull*)&sST[j * 66 + i0];
            ull p1 = *(const ull*)&sST[j * 66 + i0 + 2];
            float4 vv = *(const float4*)&sVW[j * 64 + c0];
            ull v0 = pack2(vv.x, vv.x), v1 = pack2(vv.y, vv.y);
            ull v2 = pack2(vv.z, vv.z), v3 = pack2(vv.w, vv.w);
            fma2(acc3[0][0], p0, v0); fma2(acc3[0][1], p0, v1);
            fma2(acc3[0][2], p0, v2); fma2(acc3[0][3], p0, v3);
            fma2(acc3[1][0], p1, v0); fma2(acc3[1][1], p1, v1);
            fma2(acc3[1][2], p1, v2); fma2(acc3[1][3], p1, v3);
        }

        float4 bov = *(const float4*)&sbo[c0];
        float rv[4] = { srinv[i0], srinv[i0 + 1], srinv[i0 + 2], srinv[i0 + 3] };
#pragma unroll
        for (int rp = 0; rp < 2; ++rp) {
            float2 u0 = unpack2(acc3[rp][0]);
            float2 u1 = unpack2(acc3[rp][1]);
            float2 u2 = unpack2(acc3[rp][2]);
            float2 u3 = unpack2(acc3[rp][3]);
            int ra = i0 + 2 * rp, rb = ra + 1;
            float4 oa = make_float4(u0.x * rv[2 * rp]     + bov.x,
                                    u1.x * rv[2 * rp]     + bov.y,
                                    u2.x * rv[2 * rp]     + bov.z,
                                    u3.x * rv[2 * rp]     + bov.w);
            float4 ob = make_float4(u0.y * rv[2 * rp + 1] + bov.x,
                                    u1.y * rv[2 * rp + 1] + bov.y,
                                    u2.y * rv[2 * rp + 1] + bov.z,
                                    u3.y * rv[2 * rp + 1] + bov.w);
            *(float4*)&out[(((size_t)(b << 14) + n0 + ra) << 6) + c0] = oa;
            *(float4*)&out[(((size_t)(b << 14) + n0 + rb) << 6) + c0] = ob;
        }
    }
}

// ---------------------------------------------------------------------------
extern "C" void kernel_launch(void* const* d_in, const int* in_sizes, int n_in,
                              void* d_out, int out_size)
{
    const float* inp   = (const float*)d_in[0];
    const float* Wq    = (const float*)d_in[1];
    const float* bq    = (const float*)d_in[2];
    const float* Wkv   = (const float*)d_in[3];
    const float* bkv   = (const float*)d_in[4];
    const float* Wo    = (const float*)d_in[5];
    const float* bo    = (const float*)d_in[6];
    const float* convw = (const float*)d_in[7];
    const float* convb = (const float*)d_in[8];
    const float* gamma = (const float*)d_in[9];
    const float* beta  = (const float*)d_in[10];
    float* out = (float*)d_out;

    const int smemB = 17026 * 4;   // 68104 B
    const int smemC = 54272 * 4;   // 217088 B
    cudaFuncSetAttribute(kv_kernel,   cudaFuncAttributeMaxDynamicSharedMemorySize, smemB);
    cudaFuncSetAttribute(attn_kernel, cudaFuncAttributeMaxDynamicSharedMemorySize, smemC);

    conv_kernel<<<256, 128>>>(inp, convw, convb);
    kv_kernel<<<512, 256, smemB>>>(Wq, bq, Wkv, bkv, Wo, gamma, beta);
    attn_kernel<<<dim3(256, 16), 256, smemC>>>(inp, bo, out);
}

// round 4
// speedup vs baseline: 1.7034x; 1.6244x over previous
#include <cuda_runtime.h>
#include <cstdint>

#define BATCH 16
#define NQ    16384
#define CH    64
#define NKV   256
#define EPS   1e-5f

// Scratch (device globals — no allocation allowed)
__device__ float g_xconv[BATCH * NKV * CH];   // conv output   [b*256+pos][c]
__device__ float g_G[BATCH * NKV * CH];       // Gt: [b][j][d]  pre-scaled 0.125*Wq@k
__device__ float g_VW[BATCH * CH * NKV];      // VWt: [b][c][j] (Wo^T v_j)
__device__ float g_sbias[BATCH * NKV];        // 0.125*(bq . k_j)

__device__ __forceinline__ uint32_t to_tf32(float f) {
    uint32_t r; asm("cvt.rna.tf32.f32 %0, %1;" : "=r"(r) : "f"(f)); return r;
}

// D += A(16x8) @ B(8x8), tf32 inputs, fp32 accum
__device__ __forceinline__ void mma_tf32(float* d, const uint32_t* a,
                                         uint32_t b0, uint32_t b1) {
    asm volatile(
        "mma.sync.aligned.m16n8k8.row.col.f32.tf32.tf32.f32 "
        "{%0,%1,%2,%3}, {%4,%5,%6,%7}, {%8,%9}, {%0,%1,%2,%3};"
        : "+f"(d[0]), "+f"(d[1]), "+f"(d[2]), "+f"(d[3])
        : "r"(a[0]), "r"(a[1]), "r"(a[2]), "r"(a[3]), "r"(b0), "r"(b1));
}

// ---------------------------------------------------------------------------
// Kernel A: strided conv as GEMM (R1 version — fp32 SIMT, known 113us)
// ---------------------------------------------------------------------------
__global__ void __launch_bounds__(128, 1) conv_kernel(
    const float* __restrict__ inp,
    const float* __restrict__ convw,
    const float* __restrict__ convb)
{
    __shared__ float sA[32 * 68];
    __shared__ float sB[64 * 64];

    int t  = threadIdx.x;
    int r0 = 4 * (t >> 4);
    int c0 = 4 * (t & 15);

    float acc[4][4] = {};

    int rarr[4], kkarr[4], rowbase[4];
#pragma unroll
    for (int it = 0; it < 4; ++it) {
        int f4i = it * 128 + t;
        int r   = f4i >> 4;
        int kk  = (f4i & 15) * 4;
        int rg  = blockIdx.x * 32 + r;
        int b   = rg >> 8;
        int patch = rg & 255;
        int pi  = patch >> 4, pj = patch & 15;
        rarr[it]  = r;
        kkarr[it] = kk;
        rowbase[it] = (b << 14) + (pi << 10) + (pj << 3);
    }

    for (int kc = 0; kc < 64; ++kc) {
        int di = kc >> 3, dj = kc & 7;
#pragma unroll
        for (int it = 0; it < 4; ++it) {
            const float4 v = *(const float4*)&inp[((rowbase[it] + di * 128 + dj) << 6) + kkarr[it]];
            *(float4*)&sA[rarr[it] * 68 + kkarr[it]] = v;
        }
#pragma unroll
        for (int it = 0; it < 8; ++it) {
            int f4i = it * 128 + t;
            *(float4*)&sB[f4i * 4] = *(const float4*)&convw[(kc << 12) + f4i * 4];
        }
        __syncthreads();

#pragma unroll 16
        for (int k = 0; k < 64; ++k) {
            float4 bv = *(const float4*)&sB[k * 64 + c0];
#pragma unroll
            for (int ri = 0; ri < 4; ++ri) {
                float av = sA[(r0 + ri) * 68 + k];
                acc[ri][0] += av * bv.x;
                acc[ri][1] += av * bv.y;
                acc[ri][2] += av * bv.z;
                acc[ri][3] += av * bv.w;
            }
        }
        __syncthreads();
    }

    float4 cb = *(const float4*)&convb[c0];
#pragma unroll
    for (int ri = 0; ri < 4; ++ri) {
        int rg = blockIdx.x * 32 + r0 + ri;
        float4 o = make_float4(acc[ri][0] + cb.x, acc[ri][1] + cb.y,
                               acc[ri][2] + cb.z, acc[ri][3] + cb.w);
        *(float4*)&g_xconv[rg * 64 + c0] = o;
    }
}

// ---------------------------------------------------------------------------
// Kernel B: per kv position — LN, kv proj, emit Gt[b][j][d], VWt[b][c][j], sbias
// ---------------------------------------------------------------------------
__global__ void __launch_bounds__(256, 1) kv_kernel(
    const float* __restrict__ Wq,  const float* __restrict__ bq,
    const float* __restrict__ Wkv, const float* __restrict__ bkv,
    const float* __restrict__ Wo,
    const float* __restrict__ gamma, const float* __restrict__ beta)
{
    extern __shared__ float sm[];
    float* sWkv = sm;            // 8192
    float* sWo  = sm + 8192;     // 4096
    float* sWqT = sm + 12288;    // 64*65 = 4160
    float* sx   = sm + 16448;    // 64
    float* sxn  = sm + 16512;    // 64
    float* skv  = sm + 16576;    // 128
    float* sgam = sm + 16704;    // 64
    float* sbet = sm + 16768;    // 64
    float* sbq  = sm + 16832;    // 64
    float* sbkv = sm + 16896;    // 128
    float* sstat= sm + 17024;    // 2

    int t = threadIdx.x;

#pragma unroll
    for (int it = 0; it < 8; ++it)
        ((float4*)sWkv)[it * 256 + t] = ((const float4*)Wkv)[it * 256 + t];
#pragma unroll
    for (int it = 0; it < 4; ++it)
        ((float4*)sWo)[it * 256 + t] = ((const float4*)Wo)[it * 256 + t];
#pragma unroll
    for (int it = 0; it < 4; ++it) {
        int f4i = it * 256 + t;
        int d = f4i >> 4, cc = (f4i & 15) * 4;
        float4 v = ((const float4*)Wq)[f4i];
        sWqT[(cc + 0) * 65 + d] = v.x;
        sWqT[(cc + 1) * 65 + d] = v.y;
        sWqT[(cc + 2) * 65 + d] = v.z;
        sWqT[(cc + 3) * 65 + d] = v.w;
    }
    if (t < 64)  { sgam[t] = gamma[t]; sbet[t] = beta[t]; sbq[t] = bq[t]; }
    if (t < 128) { sbkv[t] = bkv[t]; }
    __syncthreads();

    for (int p = 0; p < 8; ++p) {
        int j = blockIdx.x * 8 + p;
        if (t < 64) sx[t] = g_xconv[j * 64 + t];
        __syncthreads();

        if (t < 32) {
            float a = sx[t], b2 = sx[t + 32];
            float s = a + b2;
            float q = a * a + b2 * b2;
#pragma unroll
            for (int off = 16; off > 0; off >>= 1) {
                s += __shfl_xor_sync(0xffffffffu, s, off);
                q += __shfl_xor_sync(0xffffffffu, q, off);
            }
            if (t == 0) {
                float mean = s * (1.0f / 64.0f);
                sstat[0] = mean;
                sstat[1] = rsqrtf(q * (1.0f / 64.0f) - mean * mean + EPS);
            }
        }
        __syncthreads();
        if (t < 64)
            sxn[t] = (sx[t] - sstat[0]) * sstat[1] * sgam[t] + sbet[t];
        __syncthreads();

        if (t < 128) {
            float a = sbkv[t];
#pragma unroll 16
            for (int c = 0; c < 64; ++c)
                a += sxn[c] * sWkv[c * 128 + t];
            skv[t] = a;
        }
        __syncthreads();

        int b = j >> 8, pos = j & 255;
        if (t < 64) {
            float a = 0.0f;
#pragma unroll 16
            for (int c = 0; c < 64; ++c)
                a += sWqT[c * 65 + t] * skv[c];
            g_G[(b << 14) + pos * 64 + t] = 0.125f * a;       // Gt[b][j][d]
        } else if (t < 128) {
            int cc = t - 64;
            float a = 0.0f;
#pragma unroll 16
            for (int d = 0; d < 64; ++d)
                a += skv[64 + d] * sWo[d * 64 + cc];
            g_VW[(b << 14) + cc * 256 + pos] = a;             // VWt[b][c][j]
        } else if (t == 128) {
            float a = 0.0f;
            for (int c = 0; c < 64; ++c)
                a += sbq[c] * skv[c];
            g_sbias[(b << 8) + pos] = 0.125f * a;
        }
        __syncthreads();
    }
}

// ---------------------------------------------------------------------------
// Kernel C: mma.sync tf32 attention, per (b, 128-query tile).
//   GEMM1: S[128,256] = X[128,64] @ Gt^T  (A-frags from global, B from smem)
//   softmax (no max-subtract), P -> tf32 in place
//   GEMM2: O[128,64] = P @ VWt^T
// 8 warps (256 thr), warp w owns rows m0 = 16*w.
// smem (floats): sG 0..17408 ([j][d] ld68; later sVW [c][j] ld260),
//   sS 17408..50688 ([row][j] ld260), sbias 50688, srinv 50944, sbo 51072
//   total 51136 floats = 204544 B
// ---------------------------------------------------------------------------
#define O_G   0
#define O_S   17408
#define O_BI  50688
#define O_RI  50944
#define O_BO  51072
#define AT_SMEM (51136 * 4)

__global__ void __launch_bounds__(256, 1) attn_kernel(
    const float* __restrict__ inp,
    const float* __restrict__ bo_g,
    float* __restrict__ out)
{
    extern __shared__ float sm[];
    float* sG    = sm + O_G;
    float* sS    = sm + O_S;
    float* sbias = sm + O_BI;
    float* srinv = sm + O_RI;
    float* sbo   = sm + O_BO;

    int t = threadIdx.x, lane = t & 31, w = t >> 5;
    int lq = lane >> 2, lr = lane & 3;          // quad row / col within frags
    int m0 = w * 16;
    int b  = blockIdx.y;
    int n0 = blockIdx.x * 128;

    // ---- A-fragments of X straight from global (reused for all 32 n-blocks) ----
    uint32_t afr[8][4];
    {
        const float* x0 = inp + ((size_t)(b * NQ + n0 + m0 + lq)) * 64 + lr;
        const float* x1 = x0 + 8 * 64;
#pragma unroll
        for (int k = 0; k < 8; ++k) {
            afr[k][0] = to_tf32(x0[k * 8]);
            afr[k][1] = to_tf32(x1[k * 8]);
            afr[k][2] = to_tf32(x0[k * 8 + 4]);
            afr[k][3] = to_tf32(x1[k * 8 + 4]);
        }
    }

    // ---- stage Gt [j][d] ld 68 (tf32 bits) ----
    {
        const float4* gG = (const float4*)(g_G + (b << 14));
#pragma unroll
        for (int it = 0; it < 16; ++it) {
            int f4i = it * 256 + t;
            float4 v = gG[f4i];
            int j = f4i >> 4, d4 = (f4i & 15) * 4;
            uint4 u = make_uint4(to_tf32(v.x), to_tf32(v.y), to_tf32(v.z), to_tf32(v.w));
            *(uint4*)&sG[j * 68 + d4] = u;
        }
    }
    if (t < 64) ((float4*)sbias)[t] = ((const float4*)(g_sbias + (b << 8)))[t];
    if (t < 16) ((float4*)sbo)[t]   = ((const float4*)bo_g)[t];
    __syncthreads();

    // ---- GEMM1: S = X @ Gt^T ----
    {
        float acc[32][4];
#pragma unroll
        for (int nb = 0; nb < 32; ++nb)
#pragma unroll
            for (int i = 0; i < 4; ++i) acc[nb][i] = 0.0f;

#pragma unroll
        for (int k = 0; k < 8; ++k) {
            const float* gb = &sG[lq * 68 + k * 8 + lr];   // + nb*8*68
#pragma unroll
            for (int nb = 0; nb < 32; ++nb) {
                uint32_t b0 = __float_as_uint(gb[nb * 544]);
                uint32_t b1 = __float_as_uint(gb[nb * 544 + 4]);
                mma_tf32(acc[nb], afr[k], b0, b1);
            }
        }

        // spill S to smem [row][j] ld 260
        float* s0 = &sS[(m0 + lq) * 260 + 2 * lr];
        float* s1 = &sS[(m0 + 8 + lq) * 260 + 2 * lr];
#pragma unroll
        for (int nb = 0; nb < 32; ++nb) {
            *(float2*)&s0[nb * 8] = make_float2(acc[nb][0], acc[nb][1]);
            *(float2*)&s1[nb * 8] = make_float2(acc[nb][2], acc[nb][3]);
        }
    }
    __syncthreads();

    // ---- load VWt [c][j] ld 260 into sG region (GEMM1 done) ----
    {
        const float4* gV = (const float4*)(g_VW + (b << 14));
#pragma unroll
        for (int it = 0; it < 16; ++it) {
            int f4i = it * 256 + t;
            float4 v = gV[f4i];
            int c = f4i >> 6, j4 = (f4i & 63) * 4;
            uint4 u = make_uint4(to_tf32(v.x), to_tf32(v.y), to_tf32(v.z), to_tf32(v.w));
            *(uint4*)&sG[c * 260 + j4] = u;
        }
    }

    // ---- softmax: 4 lanes/row, rows r and r+64; +q rotation avoids conflicts ----
    {
        int r = t >> 2, q = t & 3;
#pragma unroll
        for (int pass = 0; pass < 2; ++pass) {
            int row = r + pass * 64;
            float* base = &sS[row * 260];
            float sum = 0.0f;
#pragma unroll 8
            for (int jj = 0; jj < 64; ++jj) {
                int j = q * 64 + ((jj + q) & 63);
                float e = __expf(base[j] + sbias[j]);
                sum += e;
                base[j] = __uint_as_float(to_tf32(e));
            }
            sum += __shfl_xor_sync(0xffffffffu, sum, 1);
            sum += __shfl_xor_sync(0xffffffffu, sum, 2);
            if (q == 0) srinv[row] = 1.0f / sum;
        }
    }
    __syncthreads();

    // ---- GEMM2: O = P @ VWt^T ----
    {
        float acc2[8][4];
#pragma unroll
        for (int nb = 0; nb < 8; ++nb)
#pragma unroll
            for (int i = 0; i < 4; ++i) acc2[nb][i] = 0.0f;

        const float* p0 = &sS[(m0 + lq) * 260 + lr];
        const float* p1 = &sS[(m0 + 8 + lq) * 260 + lr];
        const float* vb = &sG[lq * 260 + lr];

#pragma unroll 8
        for (int ks = 0; ks < 32; ++ks) {
            uint32_t pa[4];
            pa[0] = __float_as_uint(p0[ks * 8]);
            pa[1] = __float_as_uint(p1[ks * 8]);
            pa[2] = __float_as_uint(p0[ks * 8 + 4]);
            pa[3] = __float_as_uint(p1[ks * 8 + 4]);
#pragma unroll
            for (int nb = 0; nb < 8; ++nb) {
                uint32_t b0 = __float_as_uint(vb[nb * 2080 + ks * 8]);       // 8*260
                uint32_t b1 = __float_as_uint(vb[nb * 2080 + ks * 8 + 4]);
                mma_tf32(acc2[nb], pa, b0, b1);
            }
        }

        // epilogue
        float rv0 = srinv[m0 + lq];
        float rv1 = srinv[m0 + 8 + lq];
        size_t rg = (size_t)(b * NQ + n0 + m0 + lq) * 64;
#pragma unroll
        for (int nb = 0; nb < 8; ++nb) {
            int c = nb * 8 + 2 * lr;
            float2 o0 = make_float2(acc2[nb][0] * rv0 + sbo[c],
                                    acc2[nb][1] * rv0 + sbo[c + 1]);
            float2 o1 = make_float2(acc2[nb][2] * rv1 + sbo[c],
                                    acc2[nb][3] * rv1 + sbo[c + 1]);
            *(float2*)&out[rg + c] = o0;
            *(float2*)&out[rg + 8 * 64 + c] = o1;
        }
    }
}

// ---------------------------------------------------------------------------
extern "C" void kernel_launch(void* const* d_in, const int* in_sizes, int n_in,
                              void* d_out, int out_size)
{
    const float* inp   = (const float*)d_in[0];
    const float* Wq    = (const float*)d_in[1];
    const float* bq    = (const float*)d_in[2];
    const float* Wkv   = (const float*)d_in[3];
    const float* bkv   = (const float*)d_in[4];
    const float* Wo    = (const float*)d_in[5];
    const float* bo    = (const float*)d_in[6];
    const float* convw = (const float*)d_in[7];
    const float* convb = (const float*)d_in[8];
    const float* gamma = (const float*)d_in[9];
    const float* beta  = (const float*)d_in[10];
    float* out = (float*)d_out;

    const int smemB = 17026 * 4;
    cudaFuncSetAttribute(kv_kernel,   cudaFuncAttributeMaxDynamicSharedMemorySize, smemB);
    cudaFuncSetAttribute(attn_kernel, cudaFuncAttributeMaxDynamicSharedMemorySize, AT_SMEM);

    conv_kernel<<<128, 128>>>(inp, convw, convb);
    kv_kernel<<<512, 256, smemB>>>(Wq, bq, Wkv, bkv, Wo, gamma, beta);
    attn_kernel<<<dim3(128, 16), 256, AT_SMEM>>>(inp, bo, out);
}

// round 5
// speedup vs baseline: 1.7092x; 1.0034x over previous
#include <cuda_runtime.h>
#include <cstdint>

#define BATCH 16
#define NQ    16384
#define CH    64
#define NKV   256
#define EPS   1e-5f

// Scratch (device globals — no allocation allowed)
__device__ float g_xconv[BATCH * NKV * CH];   // conv output   [b*256+pos][c]
__device__ float g_G[BATCH * NKV * CH];       // Gt: [b][j][d]  pre-scaled 0.125*Wq@k
__device__ float g_VW[BATCH * CH * NKV];      // VWt: [b][c][j] (Wo^T v_j)
__device__ float g_sbias[BATCH * NKV];        // 0.125*(bq . k_j)

__device__ __forceinline__ uint32_t to_tf32(float f) {
    uint32_t r; asm("cvt.rna.tf32.f32 %0, %1;" : "=r"(r) : "f"(f)); return r;
}

// D += A(16x8) @ B(8x8), tf32 inputs, fp32 accum
__device__ __forceinline__ void mma_tf32(float* d, const uint32_t* a,
                                         uint32_t b0, uint32_t b1) {
    asm volatile(
        "mma.sync.aligned.m16n8k8.row.col.f32.tf32.tf32.f32 "
        "{%0,%1,%2,%3}, {%4,%5,%6,%7}, {%8,%9}, {%0,%1,%2,%3};"
        : "+f"(d[0]), "+f"(d[1]), "+f"(d[2]), "+f"(d[3])
        : "r"(a[0]), "r"(a[1]), "r"(a[2]), "r"(a[3]), "r"(b0), "r"(b1));
}

// ---------------------------------------------------------------------------
// Kernel A: strided conv as GEMM (R1 version — fp32 SIMT, known 113us)
// ---------------------------------------------------------------------------
__global__ void __launch_bounds__(128, 1) conv_kernel(
    const float* __restrict__ inp,
    const float* __restrict__ convw,
    const float* __restrict__ convb)
{
    __shared__ float sA[32 * 68];
    __shared__ float sB[64 * 64];

    int t  = threadIdx.x;
    int r0 = 4 * (t >> 4);
    int c0 = 4 * (t & 15);

    float acc[4][4] = {};

    int rarr[4], kkarr[4], rowbase[4];
#pragma unroll
    for (int it = 0; it < 4; ++it) {
        int f4i = it * 128 + t;
        int r   = f4i >> 4;
        int kk  = (f4i & 15) * 4;
        int rg  = blockIdx.x * 32 + r;
        int b   = rg >> 8;
        int patch = rg & 255;
        int pi  = patch >> 4, pj = patch & 15;
        rarr[it]  = r;
        kkarr[it] = kk;
        rowbase[it] = (b << 14) + (pi << 10) + (pj << 3);
    }

    for (int kc = 0; kc < 64; ++kc) {
        int di = kc >> 3, dj = kc & 7;
#pragma unroll
        for (int it = 0; it < 4; ++it) {
            const float4 v = *(const float4*)&inp[((rowbase[it] + di * 128 + dj) << 6) + kkarr[it]];
            *(float4*)&sA[rarr[it] * 68 + kkarr[it]] = v;
        }
#pragma unroll
        for (int it = 0; it < 8; ++it) {
            int f4i = it * 128 + t;
            *(float4*)&sB[f4i * 4] = *(const float4*)&convw[(kc << 12) + f4i * 4];
        }
        __syncthreads();

#pragma unroll 16
        for (int k = 0; k < 64; ++k) {
            float4 bv = *(const float4*)&sB[k * 64 + c0];
#pragma unroll
            for (int ri = 0; ri < 4; ++ri) {
                float av = sA[(r0 + ri) * 68 + k];
                acc[ri][0] += av * bv.x;
                acc[ri][1] += av * bv.y;
                acc[ri][2] += av * bv.z;
                acc[ri][3] += av * bv.w;
            }
        }
        __syncthreads();
    }

    float4 cb = *(const float4*)&convb[c0];
#pragma unroll
    for (int ri = 0; ri < 4; ++ri) {
        int rg = blockIdx.x * 32 + r0 + ri;
        float4 o = make_float4(acc[ri][0] + cb.x, acc[ri][1] + cb.y,
                               acc[ri][2] + cb.z, acc[ri][3] + cb.w);
        *(float4*)&g_xconv[rg * 64 + c0] = o;
    }
}

// ---------------------------------------------------------------------------
// Kernel B: per kv position — LN, kv proj, emit Gt[b][j][d], VWt[b][c][j], sbias
// ---------------------------------------------------------------------------
__global__ void __launch_bounds__(256, 1) kv_kernel(
    const float* __restrict__ Wq,  const float* __restrict__ bq,
    const float* __restrict__ Wkv, const float* __restrict__ bkv,
    const float* __restrict__ Wo,
    const float* __restrict__ gamma, const float* __restrict__ beta)
{
    extern __shared__ float sm[];
    float* sWkv = sm;            // 8192
    float* sWo  = sm + 8192;     // 4096
    float* sWqT = sm + 12288;    // 64*65 = 4160
    float* sx   = sm + 16448;    // 64
    float* sxn  = sm + 16512;    // 64
    float* skv  = sm + 16576;    // 128
    float* sgam = sm + 16704;    // 64
    float* sbet = sm + 16768;    // 64
    float* sbq  = sm + 16832;    // 64
    float* sbkv = sm + 16896;    // 128
    float* sstat= sm + 17024;    // 2

    int t = threadIdx.x;

#pragma unroll
    for (int it = 0; it < 8; ++it)
        ((float4*)sWkv)[it * 256 + t] = ((const float4*)Wkv)[it * 256 + t];
#pragma unroll
    for (int it = 0; it < 4; ++it)
        ((float4*)sWo)[it * 256 + t] = ((const float4*)Wo)[it * 256 + t];
#pragma unroll
    for (int it = 0; it < 4; ++it) {
        int f4i = it * 256 + t;
        int d = f4i >> 4, cc = (f4i & 15) * 4;
        float4 v = ((const float4*)Wq)[f4i];
        sWqT[(cc + 0) * 65 + d] = v.x;
        sWqT[(cc + 1) * 65 + d] = v.y;
        sWqT[(cc + 2) * 65 + d] = v.z;
        sWqT[(cc + 3) * 65 + d] = v.w;
    }
    if (t < 64)  { sgam[t] = gamma[t]; sbet[t] = beta[t]; sbq[t] = bq[t]; }
    if (t < 128) { sbkv[t] = bkv[t]; }
    __syncthreads();

    for (int p = 0; p < 8; ++p) {
        int j = blockIdx.x * 8 + p;
        if (t < 64) sx[t] = g_xconv[j * 64 + t];
        __syncthreads();

        if (t < 32) {
            float a = sx[t], b2 = sx[t + 32];
            float s = a + b2;
            float q = a * a + b2 * b2;
#pragma unroll
            for (int off = 16; off > 0; off >>= 1) {
                s += __shfl_xor_sync(0xffffffffu, s, off);
                q += __shfl_xor_sync(0xffffffffu, q, off);
            }
            if (t == 0) {
                float mean = s * (1.0f / 64.0f);
                sstat[0] = mean;
                sstat[1] = rsqrtf(q * (1.0f / 64.0f) - mean * mean + EPS);
            }
        }
        __syncthreads();
        if (t < 64)
            sxn[t] = (sx[t] - sstat[0]) * sstat[1] * sgam[t] + sbet[t];
        __syncthreads();

        if (t < 128) {
            float a = sbkv[t];
#pragma unroll 16
            for (int c = 0; c < 64; ++c)
                a += sxn[c] * sWkv[c * 128 + t];
            skv[t] = a;
        }
        __syncthreads();

        int b = j >> 8, pos = j & 255;
        if (t < 64) {
            float a = 0.0f;
#pragma unroll 16
            for (int c = 0; c < 64; ++c)
                a += sWqT[c * 65 + t] * skv[c];
            g_G[(b << 14) + pos * 64 + t] = 0.125f * a;       // Gt[b][j][d]
        } else if (t < 128) {
            int cc = t - 64;
            float a = 0.0f;
#pragma unroll 16
            for (int d = 0; d < 64; ++d)
                a += skv[64 + d] * sWo[d * 64 + cc];
            g_VW[(b << 14) + cc * 256 + pos] = a;             // VWt[b][c][j]
        } else if (t == 128) {
            float a = 0.0f;
            for (int c = 0; c < 64; ++c)
                a += sbq[c] * skv[c];
            g_sbias[(b << 8) + pos] = 0.125f * a;
        }
        __syncthreads();
    }
}

// ---------------------------------------------------------------------------
// Kernel C: mma.sync tf32 attention, per (b, 128-query tile).
//   GEMM1: S[128,256] = X[128,64] @ Gt^T  (A-frags from global, B from smem)
//   softmax (no max-subtract), P -> tf32 in place
//   GEMM2: O[128,64] = P @ VWt^T
// 8 warps (256 thr), warp w owns rows m0 = 16*w.
// smem (floats): sG 0..17408 ([j][d] ld68; later sVW [c][j] ld260),
//   sS 17408..50688 ([row][j] ld260), sbias 50688, srinv 50944, sbo 51072
//   total 51136 floats = 204544 B
// ---------------------------------------------------------------------------
#define O_G   0
#define O_S   17408
#define O_BI  50688
#define O_RI  50944
#define O_BO  51072
#define AT_SMEM (51136 * 4)

__global__ void __launch_bounds__(256, 1) attn_kernel(
    const float* __restrict__ inp,
    const float* __restrict__ bo_g,
    float* __restrict__ out)
{
    extern __shared__ float sm[];
    float* sG    = sm + O_G;
    float* sS    = sm + O_S;
    float* sbias = sm + O_BI;
    float* srinv = sm + O_RI;
    float* sbo   = sm + O_BO;

    int t = threadIdx.x, lane = t & 31, w = t >> 5;
    int lq = lane >> 2, lr = lane & 3;          // quad row / col within frags
    int m0 = w * 16;
    int b  = blockIdx.y;
    int n0 = blockIdx.x * 128;

    // ---- A-fragments of X straight from global (reused for all 32 n-blocks) ----
    uint32_t afr[8][4];
    {
        const float* x0 = inp + ((size_t)(b * NQ + n0 + m0 + lq)) * 64 + lr;
        const float* x1 = x0 + 8 * 64;
#pragma unroll
        for (int k = 0; k < 8; ++k) {
            afr[k][0] = to_tf32(x0[k * 8]);
            afr[k][1] = to_tf32(x1[k * 8]);
            afr[k][2] = to_tf32(x0[k * 8 + 4]);
            afr[k][3] = to_tf32(x1[k * 8 + 4]);
        }
    }

    // ---- stage Gt [j][d] ld 68 (tf32 bits) ----
    {
        const float4* gG = (const float4*)(g_G + (b << 14));
#pragma unroll
        for (int it = 0; it < 16; ++it) {
            int f4i = it * 256 + t;
            float4 v = gG[f4i];
            int j = f4i >> 4, d4 = (f4i & 15) * 4;
            uint4 u = make_uint4(to_tf32(v.x), to_tf32(v.y), to_tf32(v.z), to_tf32(v.w));
            *(uint4*)&sG[j * 68 + d4] = u;
        }
    }
    if (t < 64) ((float4*)sbias)[t] = ((const float4*)(g_sbias + (b << 8)))[t];
    if (t < 16) ((float4*)sbo)[t]   = ((const float4*)bo_g)[t];
    __syncthreads();

    // ---- GEMM1: S = X @ Gt^T ----
    {
        float acc[32][4];
#pragma unroll
        for (int nb = 0; nb < 32; ++nb)
#pragma unroll
            for (int i = 0; i < 4; ++i) acc[nb][i] = 0.0f;

#pragma unroll
        for (int k = 0; k < 8; ++k) {
            const float* gb = &sG[lq * 68 + k * 8 + lr];   // + nb*8*68
#pragma unroll
            for (int nb = 0; nb < 32; ++nb) {
                uint32_t b0 = __float_as_uint(gb[nb * 544]);
                uint32_t b1 = __float_as_uint(gb[nb * 544 + 4]);
                mma_tf32(acc[nb], afr[k], b0, b1);
            }
        }

        // spill S to smem [row][j] ld 260
        float* s0 = &sS[(m0 + lq) * 260 + 2 * lr];
        float* s1 = &sS[(m0 + 8 + lq) * 260 + 2 * lr];
#pragma unroll
        for (int nb = 0; nb < 32; ++nb) {
            *(float2*)&s0[nb * 8] = make_float2(acc[nb][0], acc[nb][1]);
            *(float2*)&s1[nb * 8] = make_float2(acc[nb][2], acc[nb][3]);
        }
    }
    __syncthreads();

    // ---- load VWt [c][j] ld 260 into sG region (GEMM1 done) ----
    {
        const float4* gV = (const float4*)(g_VW + (b << 14));
#pragma unroll
        for (int it = 0; it < 16; ++it) {
            int f4i = it * 256 + t;
            float4 v = gV[f4i];
            int c = f4i >> 6, j4 = (f4i & 63) * 4;
            uint4 u = make_uint4(to_tf32(v.x), to_tf32(v.y), to_tf32(v.z), to_tf32(v.w));
            *(uint4*)&sG[c * 260 + j4] = u;
        }
    }

    // ---- softmax: 4 lanes/row, rows r and r+64; +q rotation avoids conflicts ----
    {
        int r = t >> 2, q = t & 3;
#pragma unroll
        for (int pass = 0; pass < 2; ++pass) {
            int row = r + pass * 64;
            float* base = &sS[row * 260];
            float sum = 0.0f;
#pragma unroll 8
            for (int jj = 0; jj < 64; ++jj) {
                int j = q * 64 + ((jj + q) & 63);
                float e = __expf(base[j] + sbias[j]);
                sum += e;
                base[j] = __uint_as_float(to_tf32(e));
            }
            sum += __shfl_xor_sync(0xffffffffu, sum, 1);
            sum += __shfl_xor_sync(0xffffffffu, sum, 2);
            if (q == 0) srinv[row] = 1.0f / sum;
        }
    }
    __syncthreads();

    // ---- GEMM2: O = P @ VWt^T ----
    {
        float acc2[8][4];
#pragma unroll
        for (int nb = 0; nb < 8; ++nb)
#pragma unroll
            for (int i = 0; i < 4; ++i) acc2[nb][i] = 0.0f;

        const float* p0 = &sS[(m0 + lq) * 260 + lr];
        const float* p1 = &sS[(m0 + 8 + lq) * 260 + lr];
        const float* vb = &sG[lq * 260 + lr];

#pragma unroll 8
        for (int ks = 0; ks < 32; ++ks) {
            uint32_t pa[4];
            pa[0] = __float_as_uint(p0[ks * 8]);
            pa[1] = __float_as_uint(p1[ks * 8]);
            pa[2] = __float_as_uint(p0[ks * 8 + 4]);
            pa[3] = __float_as_uint(p1[ks * 8 + 4]);
#pragma unroll
            for (int nb = 0; nb < 8; ++nb) {
                uint32_t b0 = __float_as_uint(vb[nb * 2080 + ks * 8]);       // 8*260
                uint32_t b1 = __float_as_uint(vb[nb * 2080 + ks * 8 + 4]);
                mma_tf32(acc2[nb], pa, b0, b1);
            }
        }

        // epilogue
        float rv0 = srinv[m0 + lq];
        float rv1 = srinv[m0 + 8 + lq];
        size_t rg = (size_t)(b * NQ + n0 + m0 + lq) * 64;
#pragma unroll
        for (int nb = 0; nb < 8; ++nb) {
            int c = nb * 8 + 2 * lr;
            float2 o0 = make_float2(acc2[nb][0] * rv0 + sbo[c],
                                    acc2[nb][1] * rv0 + sbo[c + 1]);
            float2 o1 = make_float2(acc2[nb][2] * rv1 + sbo[c],
                                    acc2[nb][3] * rv1 + sbo[c + 1]);
            *(float2*)&out[rg + c] = o0;
            *(float2*)&out[rg + 8 * 64 + c] = o1;
        }
    }
}

// ---------------------------------------------------------------------------
extern "C" void kernel_launch(void* const* d_in, const int* in_sizes, int n_in,
                              void* d_out, int out_size)
{
    const float* inp   = (const float*)d_in[0];
    const float* Wq    = (const float*)d_in[1];
    const float* bq    = (const float*)d_in[2];
    const float* Wkv   = (const float*)d_in[3];
    const float* bkv   = (const float*)d_in[4];
    const float* Wo    = (const float*)d_in[5];
    const float* bo    = (const float*)d_in[6];
    const float* convw = (const float*)d_in[7];
    const float* convb = (const float*)d_in[8];
    const float* gamma = (const float*)d_in[9];
    const float* beta  = (const float*)d_in[10];
    float* out = (float*)d_out;

    const int smemB = 17026 * 4;
    cudaFuncSetAttribute(kv_kernel,   cudaFuncAttributeMaxDynamicSharedMemorySize, smemB);
    cudaFuncSetAttribute(attn_kernel, cudaFuncAttributeMaxDynamicSharedMemorySize, AT_SMEM);

    conv_kernel<<<128, 128>>>(inp, convw, convb);
    kv_kernel<<<512, 256, smemB>>>(Wq, bq, Wkv, bkv, Wo, gamma, beta);
    attn_kernel<<<dim3(128, 16), 256, AT_SMEM>>>(inp, bo, out);
}

// round 6
// speedup vs baseline: 2.9771x; 1.7418x over previous
#include <cuda_runtime.h>
#include <cstdint>

#define BATCH 16
#define NQ    16384
#define CH    64
#define NKV   256
#define EPS   1e-5f

// Scratch (device globals — no allocation allowed)
__device__ float g_xconv[BATCH * NKV * CH];   // conv output   [b*256+pos][c]
__device__ float g_G[BATCH * NKV * CH];       // Gt: [b][j][d]  pre-scaled 0.125*Wq@k
__device__ float g_VW[BATCH * CH * NKV];      // VWt: [b][c][j] (Wo^T v_j)
__device__ float g_sbias[BATCH * NKV];        // 0.125*(bq . k_j)

__device__ __forceinline__ uint32_t to_tf32(float f) {
    uint32_t r; asm("cvt.rna.tf32.f32 %0, %1;" : "=r"(r) : "f"(f)); return r;
}
__device__ __forceinline__ float tf32f(float f) {
    return __uint_as_float(to_tf32(f));
}

// D += A(16x8) @ B(8x8), tf32 inputs, fp32 accum
__device__ __forceinline__ void mma_tf32(float* d, const uint32_t* a,
                                         uint32_t b0, uint32_t b1) {
    asm volatile(
        "mma.sync.aligned.m16n8k8.row.col.f32.tf32.tf32.f32 "
        "{%0,%1,%2,%3}, {%4,%5,%6,%7}, {%8,%9}, {%0,%1,%2,%3};"
        : "+f"(d[0]), "+f"(d[1]), "+f"(d[2]), "+f"(d[3])
        : "r"(a[0]), "r"(a[1]), "r"(a[2]), "r"(a[3]), "r"(b0), "r"(b1));
}

// ---------------------------------------------------------------------------
// Kernel A: strided conv as GEMM via tf32 mma.sync.
// C[4096,64] = A[4096,4096] @ W[4096,64] + convb
// grid 128 x 32 rows, 256 threads (8 warps): warp = (rowgroup rg16 of 16) x
// (colgroup cb of 16). 64 K-chunks of 64 (one (di,dj) each), prefetched.
// sA [r][k] ld 68 (a-frag bank 4lq+lr), sW [k][c] ld 72 (b-frag bank 8lr+lq).
// ---------------------------------------------------------------------------
__global__ void __launch_bounds__(256, 1) conv_kernel(
    const float* __restrict__ inp,
    const float* __restrict__ convw,
    const float* __restrict__ convb)
{
    __shared__ float sA[32 * 68];
    __shared__ float sW[64 * 72];

    int t = threadIdx.x, lane = t & 31, w = t >> 5;
    int lq = lane >> 2, lr = lane & 3;
    int rg16 = (w >> 2) * 16;
    int cb   = (w & 3) * 16;

    // A-load metadata (2 float4-chunks per thread)
    int rarr[2], kkarr[2], rowbase[2];
#pragma unroll
    for (int it = 0; it < 2; ++it) {
        int f4i = it * 256 + t;
        int r   = f4i >> 4;
        int kk  = (f4i & 15) * 4;
        int rg  = blockIdx.x * 32 + r;
        int b   = rg >> 8;
        int patch = rg & 255;
        int pi  = patch >> 4, pj = patch & 15;
        rarr[it]  = r;
        kkarr[it] = kk;
        rowbase[it] = (b << 14) + (pi << 10) + (pj << 3);
    }
    // W-load metadata (4 float4-chunks per thread)
    int kinarr[4], c4arr[4];
#pragma unroll
    for (int it = 0; it < 4; ++it) {
        int f4i = it * 256 + t;
        kinarr[it] = f4i >> 4;
        c4arr[it]  = (f4i & 15) * 4;
    }

    float acc[2][4] = {};
    float4 pa[2], pw[4];

    // prefetch iter 0
    {
        int di = 0, dj = 0;
#pragma unroll
        for (int it = 0; it < 2; ++it)
            pa[it] = *(const float4*)&inp[((rowbase[it] + di * 128 + dj) << 6) + kkarr[it]];
#pragma unroll
        for (int it = 0; it < 4; ++it)
            pw[it] = *(const float4*)&convw[kinarr[it] * 64 + c4arr[it]];
    }

    for (int kc = 0; kc < 64; ++kc) {
        // commit prefetched tiles (tf32 converted)
#pragma unroll
        for (int it = 0; it < 2; ++it) {
            float4 v = pa[it];
            uint4 u = make_uint4(to_tf32(v.x), to_tf32(v.y), to_tf32(v.z), to_tf32(v.w));
            *(uint4*)&sA[rarr[it] * 68 + kkarr[it]] = u;
        }
#pragma unroll
        for (int it = 0; it < 4; ++it) {
            float4 v = pw[it];
            uint4 u = make_uint4(to_tf32(v.x), to_tf32(v.y), to_tf32(v.z), to_tf32(v.w));
            *(uint4*)&sW[kinarr[it] * 72 + c4arr[it]] = u;
        }
        __syncthreads();

        // prefetch next iter
        if (kc + 1 < 64) {
            int kn = kc + 1, di = kn >> 3, dj = kn & 7;
#pragma unroll
            for (int it = 0; it < 2; ++it)
                pa[it] = *(const float4*)&inp[((rowbase[it] + di * 128 + dj) << 6) + kkarr[it]];
#pragma unroll
            for (int it = 0; it < 4; ++it)
                pw[it] = *(const float4*)&convw[((kn) << 12) + kinarr[it] * 64 + c4arr[it]];
        }

        // compute: 8 k-steps x 2 nb
#pragma unroll
        for (int k = 0; k < 8; ++k) {
            uint32_t a[4];
            a[0] = __float_as_uint(sA[(rg16 + lq) * 68 + k * 8 + lr]);
            a[1] = __float_as_uint(sA[(rg16 + 8 + lq) * 68 + k * 8 + lr]);
            a[2] = __float_as_uint(sA[(rg16 + lq) * 68 + k * 8 + lr + 4]);
            a[3] = __float_as_uint(sA[(rg16 + 8 + lq) * 68 + k * 8 + lr + 4]);
#pragma unroll
            for (int nb = 0; nb < 2; ++nb) {
                uint32_t b0 = __float_as_uint(sW[(k * 8 + lr) * 72 + cb + nb * 8 + lq]);
                uint32_t b1 = __float_as_uint(sW[(k * 8 + lr + 4) * 72 + cb + nb * 8 + lq]);
                mma_tf32(acc[nb], a, b0, b1);
            }
        }
        __syncthreads();
    }

    // epilogue
    int row0 = blockIdx.x * 32 + rg16 + lq;
#pragma unroll
    for (int nb = 0; nb < 2; ++nb) {
        int c = cb + nb * 8 + 2 * lr;
        float cb0 = convb[c], cb1 = convb[c + 1];
        *(float2*)&g_xconv[row0 * 64 + c] =
            make_float2(acc[nb][0] + cb0, acc[nb][1] + cb1);
        *(float2*)&g_xconv[(row0 + 8) * 64 + c] =
            make_float2(acc[nb][2] + cb0, acc[nb][3] + cb1);
    }
}

// ---------------------------------------------------------------------------
// Kernel B: per kv position — LN, kv proj, emit Gt[b][j][d], VWt[b][c][j], sbias
// ---------------------------------------------------------------------------
__global__ void __launch_bounds__(256, 1) kv_kernel(
    const float* __restrict__ Wq,  const float* __restrict__ bq,
    const float* __restrict__ Wkv, const float* __restrict__ bkv,
    const float* __restrict__ Wo,
    const float* __restrict__ gamma, const float* __restrict__ beta)
{
    extern __shared__ float sm[];
    float* sWkv = sm;            // 8192
    float* sWo  = sm + 8192;     // 4096
    float* sWqT = sm + 12288;    // 64*65 = 4160
    float* sx   = sm + 16448;    // 64
    float* sxn  = sm + 16512;    // 64
    float* skv  = sm + 16576;    // 128
    float* sgam = sm + 16704;    // 64
    float* sbet = sm + 16768;    // 64
    float* sbq  = sm + 16832;    // 64
    float* sbkv = sm + 16896;    // 128
    float* sstat= sm + 17024;    // 2

    int t = threadIdx.x;

#pragma unroll
    for (int it = 0; it < 8; ++it)
        ((float4*)sWkv)[it * 256 + t] = ((const float4*)Wkv)[it * 256 + t];
#pragma unroll
    for (int it = 0; it < 4; ++it)
        ((float4*)sWo)[it * 256 + t] = ((const float4*)Wo)[it * 256 + t];
#pragma unroll
    for (int it = 0; it < 4; ++it) {
        int f4i = it * 256 + t;
        int d = f4i >> 4, cc = (f4i & 15) * 4;
        float4 v = ((const float4*)Wq)[f4i];
        sWqT[(cc + 0) * 65 + d] = v.x;
        sWqT[(cc + 1) * 65 + d] = v.y;
        sWqT[(cc + 2) * 65 + d] = v.z;
        sWqT[(cc + 3) * 65 + d] = v.w;
    }
    if (t < 64)  { sgam[t] = gamma[t]; sbet[t] = beta[t]; sbq[t] = bq[t]; }
    if (t < 128) { sbkv[t] = bkv[t]; }
    __syncthreads();

    for (int p = 0; p < 8; ++p) {
        int j = blockIdx.x * 8 + p;
        if (t < 64) sx[t] = g_xconv[j * 64 + t];
        __syncthreads();

        if (t < 32) {
            float a = sx[t], b2 = sx[t + 32];
            float s = a + b2;
            float q = a * a + b2 * b2;
#pragma unroll
            for (int off = 16; off > 0; off >>= 1) {
                s += __shfl_xor_sync(0xffffffffu, s, off);
                q += __shfl_xor_sync(0xffffffffu, q, off);
            }
            if (t == 0) {
                float mean = s * (1.0f / 64.0f);
                sstat[0] = mean;
                sstat[1] = rsqrtf(q * (1.0f / 64.0f) - mean * mean + EPS);
            }
        }
        __syncthreads();
        if (t < 64)
            sxn[t] = (sx[t] - sstat[0]) * sstat[1] * sgam[t] + sbet[t];
        __syncthreads();

        if (t < 128) {
            float a = sbkv[t];
#pragma unroll 16
            for (int c = 0; c < 64; ++c)
                a += sxn[c] * sWkv[c * 128 + t];
            skv[t] = a;
        }
        __syncthreads();

        int b = j >> 8, pos = j & 255;
        if (t < 64) {
            float a = 0.0f;
#pragma unroll 16
            for (int c = 0; c < 64; ++c)
                a += sWqT[c * 65 + t] * skv[c];
            g_G[(b << 14) + pos * 64 + t] = 0.125f * a;       // Gt[b][j][d]
        } else if (t < 128) {
            int cc = t - 64;
            float a = 0.0f;
#pragma unroll 16
            for (int d = 0; d < 64; ++d)
                a += skv[64 + d] * sWo[d * 64 + cc];
            g_VW[(b << 14) + cc * 256 + pos] = a;             // VWt[b][c][j]
        } else if (t == 128) {
            float a = 0.0f;
            for (int c = 0; c < 64; ++c)
                a += sbq[c] * skv[c];
            g_sbias[(b << 8) + pos] = 0.125f * a;
        }
        __syncthreads();
    }
}

// ---------------------------------------------------------------------------
// Kernel C: mma.sync tf32 attention, register-resident softmax.
//   GEMM1: S = X @ Gt^T (acc in regs, full rows per warp)
//   exp + row-sum in regs (quad shfl), P->tf32 in regs
//   C-frag -> A-frag layout conversion via quad shfls
//   GEMM2: O = P @ VWt^T; epilogue * rinv + bo
// ONE __syncthreads total (after smem staging).
// smem (floats): sG 0..17408 [j][d] ld68, sVW 17408..34048 [c][j] ld260,
//   sbias 34048, sbo 34304 -> 34368 floats = 137472 B
// ---------------------------------------------------------------------------
#define O_G   0
#define O_VW  17408
#define O_BI  34048
#define O_BO  34304
#define AT_SMEM (34368 * 4)

__global__ void __launch_bounds__(256, 1) attn_kernel(
    const float* __restrict__ inp,
    const float* __restrict__ bo_g,
    float* __restrict__ out)
{
    extern __shared__ float sm[];
    float* sG    = sm + O_G;
    float* sVW   = sm + O_VW;
    float* sbias = sm + O_BI;
    float* sbo   = sm + O_BO;

    int t = threadIdx.x, lane = t & 31, w = t >> 5;
    int lq = lane >> 2, lr = lane & 3;
    int m0 = w * 16;
    int b  = blockIdx.y;
    int n0 = blockIdx.x * 128;

    // ---- A-fragments of X straight from global ----
    uint32_t afr[8][4];
    {
        const float* x0 = inp + ((size_t)(b * NQ + n0 + m0 + lq)) * 64 + lr;
        const float* x1 = x0 + 8 * 64;
#pragma unroll
        for (int k = 0; k < 8; ++k) {
            afr[k][0] = to_tf32(x0[k * 8]);
            afr[k][1] = to_tf32(x1[k * 8]);
            afr[k][2] = to_tf32(x0[k * 8 + 4]);
            afr[k][3] = to_tf32(x1[k * 8 + 4]);
        }
    }

    // ---- stage Gt [j][d] ld68 and VWt [c][j] ld260 (both up front) ----
    {
        const float4* gG = (const float4*)(g_G + (b << 14));
#pragma unroll
        for (int it = 0; it < 16; ++it) {
            int f4i = it * 256 + t;
            float4 v = gG[f4i];
            int j = f4i >> 4, d4 = (f4i & 15) * 4;
            uint4 u = make_uint4(to_tf32(v.x), to_tf32(v.y), to_tf32(v.z), to_tf32(v.w));
            *(uint4*)&sG[j * 68 + d4] = u;
        }
        const float4* gV = (const float4*)(g_VW + (b << 14));
#pragma unroll
        for (int it = 0; it < 16; ++it) {
            int f4i = it * 256 + t;
            float4 v = gV[f4i];
            int c = f4i >> 6, j4 = (f4i & 63) * 4;
            uint4 u = make_uint4(to_tf32(v.x), to_tf32(v.y), to_tf32(v.z), to_tf32(v.w));
            *(uint4*)&sVW[c * 260 + j4] = u;
        }
    }
    if (t < 64) ((float4*)sbias)[t] = ((const float4*)(g_sbias + (b << 8)))[t];
    if (t < 16) ((float4*)sbo)[t]   = ((const float4*)bo_g)[t];
    __syncthreads();

    // ---- GEMM1: S = X @ Gt^T, full 256 cols per warp in regs ----
    float acc[32][4];
#pragma unroll
    for (int nb = 0; nb < 32; ++nb)
#pragma unroll
        for (int i = 0; i < 4; ++i) acc[nb][i] = 0.0f;

#pragma unroll
    for (int k = 0; k < 8; ++k) {
        const float* gb = &sG[lq * 68 + k * 8 + lr];   // + nb*544
#pragma unroll
        for (int nb = 0; nb < 32; ++nb) {
            uint32_t b0 = __float_as_uint(gb[nb * 544]);
            uint32_t b1 = __float_as_uint(gb[nb * 544 + 4]);
            mma_tf32(acc[nb], afr[k], b0, b1);
        }
    }

    // ---- softmax in regs: exp (no max-subtract; |S| small), quad row-sums ----
    float sum0 = 0.0f, sum1 = 0.0f;
#pragma unroll
    for (int nb = 0; nb < 32; ++nb) {
        int c = nb * 8 + 2 * lr;
        float bi0 = sbias[c], bi1 = sbias[c + 1];
        float e0 = __expf(acc[nb][0] + bi0);
        float e1 = __expf(acc[nb][1] + bi1);
        float e2 = __expf(acc[nb][2] + bi0);
        float e3 = __expf(acc[nb][3] + bi1);
        sum0 += e0 + e1;
        sum1 += e2 + e3;
        acc[nb][0] = tf32f(e0);
        acc[nb][1] = tf32f(e1);
        acc[nb][2] = tf32f(e2);
        acc[nb][3] = tf32f(e3);
    }
    sum0 += __shfl_xor_sync(0xffffffffu, sum0, 1);
    sum0 += __shfl_xor_sync(0xffffffffu, sum0, 2);
    sum1 += __shfl_xor_sync(0xffffffffu, sum1, 1);
    sum1 += __shfl_xor_sync(0xffffffffu, sum1, 2);
    float rv0 = 1.0f / sum0;
    float rv1 = 1.0f / sum1;

    // ---- GEMM2: O = P @ VWt^T (A-frags gathered from quad via shfl) ----
    float acc2[8][4];
#pragma unroll
    for (int nb = 0; nb < 8; ++nb)
#pragma unroll
        for (int i = 0; i < 4; ++i) acc2[nb][i] = 0.0f;

    int qb = lane & ~3;
    int sA0 = qb + (lr >> 1);
    int sA1 = qb + 2 + (lr >> 1);
    bool hi = (lr & 1);
    const float* vb = &sVW[lq * 260 + lr];

#pragma unroll
    for (int ks = 0; ks < 32; ++ks) {
        // P[lq][ks*8+lr], P[lq+8][ks*8+lr], P[lq][ks*8+lr+4], P[lq+8][ks*8+lr+4]
        float v00 = __shfl_sync(0xffffffffu, acc[ks][0], sA0);
        float v01 = __shfl_sync(0xffffffffu, acc[ks][1], sA0);
        float w00 = __shfl_sync(0xffffffffu, acc[ks][2], sA0);
        float w01 = __shfl_sync(0xffffffffu, acc[ks][3], sA0);
        float v10 = __shfl_sync(0xffffffffu, acc[ks][0], sA1);
        float v11 = __shfl_sync(0xffffffffu, acc[ks][1], sA1);
        float w10 = __shfl_sync(0xffffffffu, acc[ks][2], sA1);
        float w11 = __shfl_sync(0xffffffffu, acc[ks][3], sA1);
        uint32_t pa[4];
        pa[0] = __float_as_uint(hi ? v01 : v00);
        pa[1] = __float_as_uint(hi ? w01 : w00);
        pa[2] = __float_as_uint(hi ? v11 : v10);
        pa[3] = __float_as_uint(hi ? w11 : w10);
#pragma unroll
        for (int nb = 0; nb < 8; ++nb) {
            uint32_t b0 = __float_as_uint(vb[nb * 2080 + ks * 8]);     // 8*260
            uint32_t b1 = __float_as_uint(vb[nb * 2080 + ks * 8 + 4]);
            mma_tf32(acc2[nb], pa, b0, b1);
        }
    }

    // ---- epilogue ----
    {
        size_t rg = (size_t)(b * NQ + n0 + m0 + lq) * 64;
#pragma unroll
        for (int nb = 0; nb < 8; ++nb) {
            int c = nb * 8 + 2 * lr;
            float2 o0 = make_float2(acc2[nb][0] * rv0 + sbo[c],
                                    acc2[nb][1] * rv0 + sbo[c + 1]);
            float2 o1 = make_float2(acc2[nb][2] * rv1 + sbo[c],
                                    acc2[nb][3] * rv1 + sbo[c + 1]);
            *(float2*)&out[rg + c] = o0;
            *(float2*)&out[rg + 8 * 64 + c] = o1;
        }
    }
}

// ---------------------------------------------------------------------------
extern "C" void kernel_launch(void* const* d_in, const int* in_sizes, int n_in,
                              void* d_out, int out_size)
{
    const float* inp   = (const float*)d_in[0];
    const float* Wq    = (const float*)d_in[1];
    const float* bq    = (const float*)d_in[2];
    const float* Wkv   = (const float*)d_in[3];
    const float* bkv   = (const float*)d_in[4];
    const float* Wo    = (const float*)d_in[5];
    const float* bo    = (const float*)d_in[6];
    const float* convw = (const float*)d_in[7];
    const float* convb = (const float*)d_in[8];
    const float* gamma = (const float*)d_in[9];
    const float* beta  = (const float*)d_in[10];
    float* out = (float*)d_out;

    const int smemB = 17026 * 4;
    cudaFuncSetAttribute(kv_kernel,   cudaFuncAttributeMaxDynamicSharedMemorySize, smemB);
    cudaFuncSetAttribute(attn_kernel, cudaFuncAttributeMaxDynamicSharedMemorySize, AT_SMEM);

    conv_kernel<<<128, 256>>>(inp, convw, convb);
    kv_kernel<<<512, 256, smemB>>>(Wq, bq, Wkv, bkv, Wo, gamma, beta);
    attn_kernel<<<dim3(128, 16), 256, AT_SMEM>>>(inp, bo, out);
}

// round 7
// speedup vs baseline: 2.9805x; 1.0011x over previous
#include <cuda_runtime.h>
#include <cstdint>

#define BATCH 16
#define NQ    16384
#define CH    64
#define NKV   256
#define EPS   1e-5f

// Scratch (device globals — no allocation allowed)
__device__ float g_xconv[BATCH * NKV * CH];   // conv output   [b*256+pos][c]
__device__ float g_G[BATCH * NKV * CH];       // Gt: [b][j][d]  pre-scaled 0.125*Wq@k
__device__ float g_VW[BATCH * CH * NKV];      // VWt: [b][c][j] (Wo^T v_j)
__device__ float g_sbias[BATCH * NKV];        // 0.125*(bq . k_j)

__device__ __forceinline__ uint32_t to_tf32(float f) {
    uint32_t r; asm("cvt.rna.tf32.f32 %0, %1;" : "=r"(r) : "f"(f)); return r;
}
__device__ __forceinline__ float tf32f(float f) {
    return __uint_as_float(to_tf32(f));
}

// D += A(16x8) @ B(8x8), tf32 inputs, fp32 accum
__device__ __forceinline__ void mma_tf32(float* d, const uint32_t* a,
                                         uint32_t b0, uint32_t b1) {
    asm volatile(
        "mma.sync.aligned.m16n8k8.row.col.f32.tf32.tf32.f32 "
        "{%0,%1,%2,%3}, {%4,%5,%6,%7}, {%8,%9}, {%0,%1,%2,%3};"
        : "+f"(d[0]), "+f"(d[1]), "+f"(d[2]), "+f"(d[3])
        : "r"(a[0]), "r"(a[1]), "r"(a[2]), "r"(a[3]), "r"(b0), "r"(b1));
}

// ---------------------------------------------------------------------------
// Kernel A: strided conv as GEMM via tf32 mma.sync.
// C[4096,64] = A[4096,4096] @ W[4096,64] + convb
// grid 128 x 32 rows, 256 threads (8 warps): warp = (rowgroup rg16 of 16) x
// (colgroup cb of 16). 64 K-chunks of 64 (one (di,dj) each), prefetched.
// sA [r][k] ld 68 (a-frag bank 4lq+lr), sW [k][c] ld 72 (b-frag bank 8lr+lq).
// ---------------------------------------------------------------------------
__global__ void __launch_bounds__(256, 1) conv_kernel(
    const float* __restrict__ inp,
    const float* __restrict__ convw,
    const float* __restrict__ convb)
{
    __shared__ float sA[32 * 68];
    __shared__ float sW[64 * 72];

    int t = threadIdx.x, lane = t & 31, w = t >> 5;
    int lq = lane >> 2, lr = lane & 3;
    int rg16 = (w >> 2) * 16;
    int cb   = (w & 3) * 16;

    // A-load metadata (2 float4-chunks per thread)
    int rarr[2], kkarr[2], rowbase[2];
#pragma unroll
    for (int it = 0; it < 2; ++it) {
        int f4i = it * 256 + t;
        int r   = f4i >> 4;
        int kk  = (f4i & 15) * 4;
        int rg  = blockIdx.x * 32 + r;
        int b   = rg >> 8;
        int patch = rg & 255;
        int pi  = patch >> 4, pj = patch & 15;
        rarr[it]  = r;
        kkarr[it] = kk;
        rowbase[it] = (b << 14) + (pi << 10) + (pj << 3);
    }
    // W-load metadata (4 float4-chunks per thread)
    int kinarr[4], c4arr[4];
#pragma unroll
    for (int it = 0; it < 4; ++it) {
        int f4i = it * 256 + t;
        kinarr[it] = f4i >> 4;
        c4arr[it]  = (f4i & 15) * 4;
    }

    float acc[2][4] = {};
    float4 pa[2], pw[4];

    // prefetch iter 0
    {
        int di = 0, dj = 0;
#pragma unroll
        for (int it = 0; it < 2; ++it)
            pa[it] = *(const float4*)&inp[((rowbase[it] + di * 128 + dj) << 6) + kkarr[it]];
#pragma unroll
        for (int it = 0; it < 4; ++it)
            pw[it] = *(const float4*)&convw[kinarr[it] * 64 + c4arr[it]];
    }

    for (int kc = 0; kc < 64; ++kc) {
        // commit prefetched tiles (tf32 converted)
#pragma unroll
        for (int it = 0; it < 2; ++it) {
            float4 v = pa[it];
            uint4 u = make_uint4(to_tf32(v.x), to_tf32(v.y), to_tf32(v.z), to_tf32(v.w));
            *(uint4*)&sA[rarr[it] * 68 + kkarr[it]] = u;
        }
#pragma unroll
        for (int it = 0; it < 4; ++it) {
            float4 v = pw[it];
            uint4 u = make_uint4(to_tf32(v.x), to_tf32(v.y), to_tf32(v.z), to_tf32(v.w));
            *(uint4*)&sW[kinarr[it] * 72 + c4arr[it]] = u;
        }
        __syncthreads();

        // prefetch next iter
        if (kc + 1 < 64) {
            int kn = kc + 1, di = kn >> 3, dj = kn & 7;
#pragma unroll
            for (int it = 0; it < 2; ++it)
                pa[it] = *(const float4*)&inp[((rowbase[it] + di * 128 + dj) << 6) + kkarr[it]];
#pragma unroll
            for (int it = 0; it < 4; ++it)
                pw[it] = *(const float4*)&convw[((kn) << 12) + kinarr[it] * 64 + c4arr[it]];
        }

        // compute: 8 k-steps x 2 nb
#pragma unroll
        for (int k = 0; k < 8; ++k) {
            uint32_t a[4];
            a[0] = __float_as_uint(sA[(rg16 + lq) * 68 + k * 8 + lr]);
            a[1] = __float_as_uint(sA[(rg16 + 8 + lq) * 68 + k * 8 + lr]);
            a[2] = __float_as_uint(sA[(rg16 + lq) * 68 + k * 8 + lr + 4]);
            a[3] = __float_as_uint(sA[(rg16 + 8 + lq) * 68 + k * 8 + lr + 4]);
#pragma unroll
            for (int nb = 0; nb < 2; ++nb) {
                uint32_t b0 = __float_as_uint(sW[(k * 8 + lr) * 72 + cb + nb * 8 + lq]);
                uint32_t b1 = __float_as_uint(sW[(k * 8 + lr + 4) * 72 + cb + nb * 8 + lq]);
                mma_tf32(acc[nb], a, b0, b1);
            }
        }
        __syncthreads();
    }

    // epilogue
    int row0 = blockIdx.x * 32 + rg16 + lq;
#pragma unroll
    for (int nb = 0; nb < 2; ++nb) {
        int c = cb + nb * 8 + 2 * lr;
        float cb0 = convb[c], cb1 = convb[c + 1];
        *(float2*)&g_xconv[row0 * 64 + c] =
            make_float2(acc[nb][0] + cb0, acc[nb][1] + cb1);
        *(float2*)&g_xconv[(row0 + 8) * 64 + c] =
            make_float2(acc[nb][2] + cb0, acc[nb][3] + cb1);
    }
}

// ---------------------------------------------------------------------------
// Kernel B: per kv position — LN, kv proj, emit Gt[b][j][d], VWt[b][c][j], sbias
// ---------------------------------------------------------------------------
__global__ void __launch_bounds__(256, 1) kv_kernel(
    const float* __restrict__ Wq,  const float* __restrict__ bq,
    const float* __restrict__ Wkv, const float* __restrict__ bkv,
    const float* __restrict__ Wo,
    const float* __restrict__ gamma, const float* __restrict__ beta)
{
    extern __shared__ float sm[];
    float* sWkv = sm;            // 8192
    float* sWo  = sm + 8192;     // 4096
    float* sWqT = sm + 12288;    // 64*65 = 4160
    float* sx   = sm + 16448;    // 64
    float* sxn  = sm + 16512;    // 64
    float* skv  = sm + 16576;    // 128
    float* sgam = sm + 16704;    // 64
    float* sbet = sm + 16768;    // 64
    float* sbq  = sm + 16832;    // 64
    float* sbkv = sm + 16896;    // 128
    float* sstat= sm + 17024;    // 2

    int t = threadIdx.x;

#pragma unroll
    for (int it = 0; it < 8; ++it)
        ((float4*)sWkv)[it * 256 + t] = ((const float4*)Wkv)[it * 256 + t];
#pragma unroll
    for (int it = 0; it < 4; ++it)
        ((float4*)sWo)[it * 256 + t] = ((const float4*)Wo)[it * 256 + t];
#pragma unroll
    for (int it = 0; it < 4; ++it) {
        int f4i = it * 256 + t;
        int d = f4i >> 4, cc = (f4i & 15) * 4;
        float4 v = ((const float4*)Wq)[f4i];
        sWqT[(cc + 0) * 65 + d] = v.x;
        sWqT[(cc + 1) * 65 + d] = v.y;
        sWqT[(cc + 2) * 65 + d] = v.z;
        sWqT[(cc + 3) * 65 + d] = v.w;
    }
    if (t < 64)  { sgam[t] = gamma[t]; sbet[t] = beta[t]; sbq[t] = bq[t]; }
    if (t < 128) { sbkv[t] = bkv[t]; }
    __syncthreads();

    for (int p = 0; p < 8; ++p) {
        int j = blockIdx.x * 8 + p;
        if (t < 64) sx[t] = g_xconv[j * 64 + t];
        __syncthreads();

        if (t < 32) {
            float a = sx[t], b2 = sx[t + 32];
            float s = a + b2;
            float q = a * a + b2 * b2;
#pragma unroll
            for (int off = 16; off > 0; off >>= 1) {
                s += __shfl_xor_sync(0xffffffffu, s, off);
                q += __shfl_xor_sync(0xffffffffu, q, off);
            }
            if (t == 0) {
                float mean = s * (1.0f / 64.0f);
                sstat[0] = mean;
                sstat[1] = rsqrtf(q * (1.0f / 64.0f) - mean * mean + EPS);
            }
        }
        __syncthreads();
        if (t < 64)
            sxn[t] = (sx[t] - sstat[0]) * sstat[1] * sgam[t] + sbet[t];
        __syncthreads();

        if (t < 128) {
            float a = sbkv[t];
#pragma unroll 16
            for (int c = 0; c < 64; ++c)
                a += sxn[c] * sWkv[c * 128 + t];
            skv[t] = a;
        }
        __syncthreads();

        int b = j >> 8, pos = j & 255;
        if (t < 64) {
            float a = 0.0f;
#pragma unroll 16
            for (int c = 0; c < 64; ++c)
                a += sWqT[c * 65 + t] * skv[c];
            g_G[(b << 14) + pos * 64 + t] = 0.125f * a;       // Gt[b][j][d]
        } else if (t < 128) {
            int cc = t - 64;
            float a = 0.0f;
#pragma unroll 16
            for (int d = 0; d < 64; ++d)
                a += skv[64 + d] * sWo[d * 64 + cc];
            g_VW[(b << 14) + cc * 256 + pos] = a;             // VWt[b][c][j]
        } else if (t == 128) {
            float a = 0.0f;
            for (int c = 0; c < 64; ++c)
                a += sbq[c] * skv[c];
            g_sbias[(b << 8) + pos] = 0.125f * a;
        }
        __syncthreads();
    }
}

// ---------------------------------------------------------------------------
// Kernel C: mma.sync tf32 attention, register-resident softmax.
//   GEMM1: S = X @ Gt^T (acc in regs, full rows per warp)
//   exp + row-sum in regs (quad shfl), P->tf32 in regs
//   C-frag -> A-frag layout conversion via quad shfls
//   GEMM2: O = P @ VWt^T; epilogue * rinv + bo
// ONE __syncthreads total (after smem staging).
// smem (floats): sG 0..17408 [j][d] ld68, sVW 17408..34048 [c][j] ld260,
//   sbias 34048, sbo 34304 -> 34368 floats = 137472 B
// ---------------------------------------------------------------------------
#define O_G   0
#define O_VW  17408
#define O_BI  34048
#define O_BO  34304
#define AT_SMEM (34368 * 4)

__global__ void __launch_bounds__(256, 1) attn_kernel(
    const float* __restrict__ inp,
    const float* __restrict__ bo_g,
    float* __restrict__ out)
{
    extern __shared__ float sm[];
    float* sG    = sm + O_G;
    float* sVW   = sm + O_VW;
    float* sbias = sm + O_BI;
    float* sbo   = sm + O_BO;

    int t = threadIdx.x, lane = t & 31, w = t >> 5;
    int lq = lane >> 2, lr = lane & 3;
    int m0 = w * 16;
    int b  = blockIdx.y;
    int n0 = blockIdx.x * 128;

    // ---- A-fragments of X straight from global ----
    uint32_t afr[8][4];
    {
        const float* x0 = inp + ((size_t)(b * NQ + n0 + m0 + lq)) * 64 + lr;
        const float* x1 = x0 + 8 * 64;
#pragma unroll
        for (int k = 0; k < 8; ++k) {
            afr[k][0] = to_tf32(x0[k * 8]);
            afr[k][1] = to_tf32(x1[k * 8]);
            afr[k][2] = to_tf32(x0[k * 8 + 4]);
            afr[k][3] = to_tf32(x1[k * 8 + 4]);
        }
    }

    // ---- stage Gt [j][d] ld68 and VWt [c][j] ld260 (both up front) ----
    {
        const float4* gG = (const float4*)(g_G + (b << 14));
#pragma unroll
        for (int it = 0; it < 16; ++it) {
            int f4i = it * 256 + t;
            float4 v = gG[f4i];
            int j = f4i >> 4, d4 = (f4i & 15) * 4;
            uint4 u = make_uint4(to_tf32(v.x), to_tf32(v.y), to_tf32(v.z), to_tf32(v.w));
            *(uint4*)&sG[j * 68 + d4] = u;
        }
        const float4* gV = (const float4*)(g_VW + (b << 14));
#pragma unroll
        for (int it = 0; it < 16; ++it) {
            int f4i = it * 256 + t;
            float4 v = gV[f4i];
            int c = f4i >> 6, j4 = (f4i & 63) * 4;
            uint4 u = make_uint4(to_tf32(v.x), to_tf32(v.y), to_tf32(v.z), to_tf32(v.w));
            *(uint4*)&sVW[c * 260 + j4] = u;
        }
    }
    if (t < 64) ((float4*)sbias)[t] = ((const float4*)(g_sbias + (b << 8)))[t];
    if (t < 16) ((float4*)sbo)[t]   = ((const float4*)bo_g)[t];
    __syncthreads();

    // ---- GEMM1: S = X @ Gt^T, full 256 cols per warp in regs ----
    float acc[32][4];
#pragma unroll
    for (int nb = 0; nb < 32; ++nb)
#pragma unroll
        for (int i = 0; i < 4; ++i) acc[nb][i] = 0.0f;

#pragma unroll
    for (int k = 0; k < 8; ++k) {
        const float* gb = &sG[lq * 68 + k * 8 + lr];   // + nb*544
#pragma unroll
        for (int nb = 0; nb < 32; ++nb) {
            uint32_t b0 = __float_as_uint(gb[nb * 544]);
            uint32_t b1 = __float_as_uint(gb[nb * 544 + 4]);
            mma_tf32(acc[nb], afr[k], b0, b1);
        }
    }

    // ---- softmax in regs: exp (no max-subtract; |S| small), quad row-sums ----
    float sum0 = 0.0f, sum1 = 0.0f;
#pragma unroll
    for (int nb = 0; nb < 32; ++nb) {
        int c = nb * 8 + 2 * lr;
        float bi0 = sbias[c], bi1 = sbias[c + 1];
        float e0 = __expf(acc[nb][0] + bi0);
        float e1 = __expf(acc[nb][1] + bi1);
        float e2 = __expf(acc[nb][2] + bi0);
        float e3 = __expf(acc[nb][3] + bi1);
        sum0 += e0 + e1;
        sum1 += e2 + e3;
        acc[nb][0] = tf32f(e0);
        acc[nb][1] = tf32f(e1);
        acc[nb][2] = tf32f(e2);
        acc[nb][3] = tf32f(e3);
    }
    sum0 += __shfl_xor_sync(0xffffffffu, sum0, 1);
    sum0 += __shfl_xor_sync(0xffffffffu, sum0, 2);
    sum1 += __shfl_xor_sync(0xffffffffu, sum1, 1);
    sum1 += __shfl_xor_sync(0xffffffffu, sum1, 2);
    float rv0 = 1.0f / sum0;
    float rv1 = 1.0f / sum1;

    // ---- GEMM2: O = P @ VWt^T (A-frags gathered from quad via shfl) ----
    float acc2[8][4];
#pragma unroll
    for (int nb = 0; nb < 8; ++nb)
#pragma unroll
        for (int i = 0; i < 4; ++i) acc2[nb][i] = 0.0f;

    int qb = lane & ~3;
    int sA0 = qb + (lr >> 1);
    int sA1 = qb + 2 + (lr >> 1);
    bool hi = (lr & 1);
    const float* vb = &sVW[lq * 260 + lr];

#pragma unroll
    for (int ks = 0; ks < 32; ++ks) {
        // P[lq][ks*8+lr], P[lq+8][ks*8+lr], P[lq][ks*8+lr+4], P[lq+8][ks*8+lr+4]
        float v00 = __shfl_sync(0xffffffffu, acc[ks][0], sA0);
        float v01 = __shfl_sync(0xffffffffu, acc[ks][1], sA0);
        float w00 = __shfl_sync(0xffffffffu, acc[ks][2], sA0);
        float w01 = __shfl_sync(0xffffffffu, acc[ks][3], sA0);
        float v10 = __shfl_sync(0xffffffffu, acc[ks][0], sA1);
        float v11 = __shfl_sync(0xffffffffu, acc[ks][1], sA1);
        float w10 = __shfl_sync(0xffffffffu, acc[ks][2], sA1);
        float w11 = __shfl_sync(0xffffffffu, acc[ks][3], sA1);
        uint32_t pa[4];
        pa[0] = __float_as_uint(hi ? v01 : v00);
        pa[1] = __float_as_uint(hi ? w01 : w00);
        pa[2] = __float_as_uint(hi ? v11 : v10);
        pa[3] = __float_as_uint(hi ? w11 : w10);
#pragma unroll
        for (int nb = 0; nb < 8; ++nb) {
            uint32_t b0 = __float_as_uint(vb[nb * 2080 + ks * 8]);     // 8*260
            uint32_t b1 = __float_as_uint(vb[nb * 2080 + ks * 8 + 4]);
            mma_tf32(acc2[nb], pa, b0, b1);
        }
    }

    // ---- epilogue ----
    {
        size_t rg = (size_t)(b * NQ + n0 + m0 + lq) * 64;
#pragma unroll
        for (int nb = 0; nb < 8; ++nb) {
            int c = nb * 8 + 2 * lr;
            float2 o0 = make_float2(acc2[nb][0] * rv0 + sbo[c],
                                    acc2[nb][1] * rv0 + sbo[c + 1]);
            float2 o1 = make_float2(acc2[nb][2] * rv1 + sbo[c],
                                    acc2[nb][3] * rv1 + sbo[c + 1]);
            *(float2*)&out[rg + c] = o0;
            *(float2*)&out[rg + 8 * 64 + c] = o1;
        }
    }
}

// ---------------------------------------------------------------------------
extern "C" void kernel_launch(void* const* d_in, const int* in_sizes, int n_in,
                              void* d_out, int out_size)
{
    const float* inp   = (const float*)d_in[0];
    const float* Wq    = (const float*)d_in[1];
    const float* bq    = (const float*)d_in[2];
    const float* Wkv   = (const float*)d_in[3];
    const float* bkv   = (const float*)d_in[4];
    const float* Wo    = (const float*)d_in[5];
    const float* bo    = (const float*)d_in[6];
    const float* convw = (const float*)d_in[7];
    const float* convb = (const float*)d_in[8];
    const float* gamma = (const float*)d_in[9];
    const float* beta  = (const float*)d_in[10];
    float* out = (float*)d_out;

    const int smemB = 17026 * 4;
    cudaFuncSetAttribute(kv_kernel,   cudaFuncAttributeMaxDynamicSharedMemorySize, smemB);
    cudaFuncSetAttribute(attn_kernel, cudaFuncAttributeMaxDynamicSharedMemorySize, AT_SMEM);

    conv_kernel<<<128, 256>>>(inp, convw, convb);
    kv_kernel<<<512, 256, smemB>>>(Wq, bq, Wkv, bkv, Wo, gamma, beta);
    attn_kernel<<<dim3(128, 16), 256, AT_SMEM>>>(inp, bo, out);
}

// round 9
// speedup vs baseline: 4.0973x; 1.3747x over previous
#include <cuda_runtime.h>
#include <cuda_fp16.h>
#include <cstdint>

#define BATCH 16
#define NQ    16384
#define CH    64
#define NKV   256
#define EPS   1e-5f

// Scratch (device globals — no allocation allowed)
__device__ float  g_xconv[BATCH * NKV * CH];  // conv output [b*256+pos][c]
__device__ __half g_Gh[BATCH * 16384];        // G fragments  [b][nt32][ks4][lane32][w2][h2]
__device__ __half g_VWh[BATCH * 16384];       // VW fragments [b][ct8][ks16][lane32][w2][h2]
__device__ float  g_sbias[BATCH * NKV];       // 0.125*(bq . k_j)

__device__ __forceinline__ uint32_t to_tf32(float f) {
    uint32_t r; asm("cvt.rna.tf32.f32 %0, %1;" : "=r"(r) : "f"(f)); return r;
}
__device__ __forceinline__ uint32_t pack_h2(float lo, float hi) {
    __half2 h = __floats2half2_rn(lo, hi);
    return *(uint32_t*)&h;
}

// tf32: D += A(16x8) @ B(8x8)
__device__ __forceinline__ void mma_tf32(float* d, const uint32_t* a,
                                         uint32_t b0, uint32_t b1) {
    asm volatile(
        "mma.sync.aligned.m16n8k8.row.col.f32.tf32.tf32.f32 "
        "{%0,%1,%2,%3}, {%4,%5,%6,%7}, {%8,%9}, {%0,%1,%2,%3};"
        : "+f"(d[0]), "+f"(d[1]), "+f"(d[2]), "+f"(d[3])
        : "r"(a[0]), "r"(a[1]), "r"(a[2]), "r"(a[3]), "r"(b0), "r"(b1));
}
// fp16: D += A(16x16) @ B(16x8), fp32 accum
__device__ __forceinline__ void mma_f16(float* d, const uint32_t* a,
                                        uint32_t b0, uint32_t b1) {
    asm volatile(
        "mma.sync.aligned.m16n8k16.row.col.f32.f16.f16.f32 "
        "{%0,%1,%2,%3}, {%4,%5,%6,%7}, {%8,%9}, {%0,%1,%2,%3};"
        : "+f"(d[0]), "+f"(d[1]), "+f"(d[2]), "+f"(d[3])
        : "r"(a[0]), "r"(a[1]), "r"(a[2]), "r"(a[3]), "r"(b0), "r"(b1));
}

// ---------------------------------------------------------------------------
// Kernel A: strided conv as GEMM via tf32 mma.sync (R7, 46.8us)
// ---------------------------------------------------------------------------
__global__ void __launch_bounds__(256, 1) conv_kernel(
    const float* __restrict__ inp,
    const float* __restrict__ convw,
    const float* __restrict__ convb)
{
    __shared__ float sA[32 * 68];
    __shared__ float sW[64 * 72];

    int t = threadIdx.x, lane = t & 31, w = t >> 5;
    int lq = lane >> 2, lr = lane & 3;
    int rg16 = (w >> 2) * 16;
    int cb   = (w & 3) * 16;

    int rarr[2], kkarr[2], rowbase[2];
#pragma unroll
    for (int it = 0; it < 2; ++it) {
        int f4i = it * 256 + t;
        int r   = f4i >> 4;
        int kk  = (f4i & 15) * 4;
        int rg  = blockIdx.x * 32 + r;
        int b   = rg >> 8;
        int patch = rg & 255;
        int pi  = patch >> 4, pj = patch & 15;
        rarr[it]  = r;
        kkarr[it] = kk;
        rowbase[it] = (b << 14) + (pi << 10) + (pj << 3);
    }
    int kinarr[4], c4arr[4];
#pragma unroll
    for (int it = 0; it < 4; ++it) {
        int f4i = it * 256 + t;
        kinarr[it] = f4i >> 4;
        c4arr[it]  = (f4i & 15) * 4;
    }

    float acc[2][4] = {};
    float4 pa[2], pw[4];

    {
#pragma unroll
        for (int it = 0; it < 2; ++it)
            pa[it] = *(const float4*)&inp[(rowbase[it] << 6) + kkarr[it]];
#pragma unroll
        for (int it = 0; it < 4; ++it)
            pw[it] = *(const float4*)&convw[kinarr[it] * 64 + c4arr[it]];
    }

    for (int kc = 0; kc < 64; ++kc) {
#pragma unroll
        for (int it = 0; it < 2; ++it) {
            float4 v = pa[it];
            uint4 u = make_uint4(to_tf32(v.x), to_tf32(v.y), to_tf32(v.z), to_tf32(v.w));
            *(uint4*)&sA[rarr[it] * 68 + kkarr[it]] = u;
        }
#pragma unroll
        for (int it = 0; it < 4; ++it) {
            float4 v = pw[it];
            uint4 u = make_uint4(to_tf32(v.x), to_tf32(v.y), to_tf32(v.z), to_tf32(v.w));
            *(uint4*)&sW[kinarr[it] * 72 + c4arr[it]] = u;
        }
        __syncthreads();

        if (kc + 1 < 64) {
            int kn = kc + 1, di = kn >> 3, dj = kn & 7;
#pragma unroll
            for (int it = 0; it < 2; ++it)
                pa[it] = *(const float4*)&inp[((rowbase[it] + di * 128 + dj) << 6) + kkarr[it]];
#pragma unroll
            for (int it = 0; it < 4; ++it)
                pw[it] = *(const float4*)&convw[(kn << 12) + kinarr[it] * 64 + c4arr[it]];
        }

#pragma unroll
        for (int k = 0; k < 8; ++k) {
            uint32_t a[4];
            a[0] = __float_as_uint(sA[(rg16 + lq) * 68 + k * 8 + lr]);
            a[1] = __float_as_uint(sA[(rg16 + 8 + lq) * 68 + k * 8 + lr]);
            a[2] = __float_as_uint(sA[(rg16 + lq) * 68 + k * 8 + lr + 4]);
            a[3] = __float_as_uint(sA[(rg16 + 8 + lq) * 68 + k * 8 + lr + 4]);
#pragma unroll
            for (int nb = 0; nb < 2; ++nb) {
                uint32_t b0 = __float_as_uint(sW[(k * 8 + lr) * 72 + cb + nb * 8 + lq]);
                uint32_t b1 = __float_as_uint(sW[(k * 8 + lr + 4) * 72 + cb + nb * 8 + lq]);
                mma_tf32(acc[nb], a, b0, b1);
            }
        }
        __syncthreads();
    }

    int row0 = blockIdx.x * 32 + rg16 + lq;
#pragma unroll
    for (int nb = 0; nb < 2; ++nb) {
        int c = cb + nb * 8 + 2 * lr;
        float cb0 = convb[c], cb1 = convb[c + 1];
        *(float2*)&g_xconv[row0 * 64 + c] =
            make_float2(acc[nb][0] + cb0, acc[nb][1] + cb1);
        *(float2*)&g_xconv[(row0 + 8) * 64 + c] =
            make_float2(acc[nb][2] + cb0, acc[nb][3] + cb1);
    }
}

// ---------------------------------------------------------------------------
// Kernel B: per kv position — LN, kv proj; emits FRAGMENT-ORDERED fp16 G/VW.
// G  frag (GEMM1 B, k=d): idx = ((((b*32+nt)*4+ks)*32 + lq*4+lr)*2 + w)*2 + h
//   with nt=pos>>3, lq=pos&7, ks=d>>4, dd=d&15, w=dd>>3, lr=(dd>>1)&3, h=dd&1
// VW frag (GEMM2 B, k=j):  idx = ((((b*8+ct)*16+ks)*32 + lq*4+lr)*2 + w)*2 + h
//   with ct=c>>3, lq=c&7, ks=pos>>4, jj=pos&15, w=jj>>3, lr=(jj>>1)&3, h=jj&1
// ---------------------------------------------------------------------------
__global__ void __launch_bounds__(256, 1) kv_kernel(
    const float* __restrict__ Wq,  const float* __restrict__ bq,
    const float* __restrict__ Wkv, const float* __restrict__ bkv,
    const float* __restrict__ Wo,
    const float* __restrict__ gamma, const float* __restrict__ beta)
{
    extern __shared__ float sm[];
    float* sWkv = sm;            // 8192
    float* sWo  = sm + 8192;     // 4096
    float* sWqT = sm + 12288;    // 64*65
    float* sx   = sm + 16448;
    float* sxn  = sm + 16512;
    float* skv  = sm + 16576;
    float* sgam = sm + 16704;
    float* sbet = sm + 16768;
    float* sbq  = sm + 16832;
    float* sbkv = sm + 16896;
    float* sstat= sm + 17024;

    int t = threadIdx.x;

#pragma unroll
    for (int it = 0; it < 8; ++it)
        ((float4*)sWkv)[it * 256 + t] = ((const float4*)Wkv)[it * 256 + t];
#pragma unroll
    for (int it = 0; it < 4; ++it)
        ((float4*)sWo)[it * 256 + t] = ((const float4*)Wo)[it * 256 + t];
#pragma unroll
    for (int it = 0; it < 4; ++it) {
        int f4i = it * 256 + t;
        int d = f4i >> 4, cc = (f4i & 15) * 4;
        float4 v = ((const float4*)Wq)[f4i];
        sWqT[(cc + 0) * 65 + d] = v.x;
        sWqT[(cc + 1) * 65 + d] = v.y;
        sWqT[(cc + 2) * 65 + d] = v.z;
        sWqT[(cc + 3) * 65 + d] = v.w;
    }
    if (t < 64)  { sgam[t] = gamma[t]; sbet[t] = beta[t]; sbq[t] = bq[t]; }
    if (t < 128) { sbkv[t] = bkv[t]; }
    __syncthreads();

    for (int p = 0; p < 8; ++p) {
        int j = blockIdx.x * 8 + p;
        if (t < 64) sx[t] = g_xconv[j * 64 + t];
        __syncthreads();

        if (t < 32) {
            float a = sx[t], b2 = sx[t + 32];
            float s = a + b2;
            float q = a * a + b2 * b2;
#pragma unroll
            for (int off = 16; off > 0; off >>= 1) {
                s += __shfl_xor_sync(0xffffffffu, s, off);
                q += __shfl_xor_sync(0xffffffffu, q, off);
            }
            if (t == 0) {
                float mean = s * (1.0f / 64.0f);
                sstat[0] = mean;
                sstat[1] = rsqrtf(q * (1.0f / 64.0f) - mean * mean + EPS);
            }
        }
        __syncthreads();
        if (t < 64)
            sxn[t] = (sx[t] - sstat[0]) * sstat[1] * sgam[t] + sbet[t];
        __syncthreads();

        if (t < 128) {
            float a = sbkv[t];
#pragma unroll 16
            for (int c = 0; c < 64; ++c)
                a += sxn[c] * sWkv[c * 128 + t];
            skv[t] = a;
        }
        __syncthreads();

        int b = j >> 8, pos = j & 255;
        if (t < 64) {
            float a = 0.0f;
#pragma unroll 16
            for (int c = 0; c < 64; ++c)
                a += sWqT[c * 65 + t] * skv[c];
            // fragment-ordered fp16 write of G[pos][d=t]
            int nt = pos >> 3, lqj = pos & 7;
            int d = t, ks = d >> 4, dd = d & 15;
            int wrd = dd >> 3, lr = (dd >> 1) & 3, h = dd & 1;
            int idx = ((((b * 32 + nt) * 4 + ks) * 32 + lqj * 4 + lr) * 2 + wrd) * 2 + h;
            g_Gh[idx] = __float2half_rn(0.125f * a);
        } else if (t < 128) {
            int cc = t - 64;
            float a = 0.0f;
#pragma unroll 16
            for (int d = 0; d < 64; ++d)
                a += skv[64 + d] * sWo[d * 64 + cc];
            // fragment-ordered fp16 write of VW[cc][pos]
            int ct = cc >> 3, lqc = cc & 7;
            int ks = pos >> 4, jj = pos & 15;
            int wrd = jj >> 3, lr = (jj >> 1) & 3, h = jj & 1;
            int idx = ((((b * 8 + ct) * 16 + ks) * 32 + lqc * 4 + lr) * 2 + wrd) * 2 + h;
            g_VWh[idx] = __float2half_rn(a);
        } else if (t == 128) {
            float a = 0.0f;
            for (int c = 0; c < 64; ++c)
                a += sbq[c] * skv[c];
            g_sbias[(b << 8) + pos] = 0.125f * a;
        }
        __syncthreads();
    }
}

// ---------------------------------------------------------------------------
// Kernel C: fp16 m16n8k16 attention; fragment-ordered B, register softmax,
// zero-shuffle P handoff (GEMM1 C-frag pair == GEMM2 A-frag).
// smem: sG 32KB (uint2-addressable frags), sVW 32KB, sbias 1KB, sbo 256B
// ---------------------------------------------------------------------------
#define AT_SMEM (32768 + 32768 + 1024 + 256)

__global__ void __launch_bounds__(256, 1) attn_kernel(
    const float* __restrict__ inp,
    const float* __restrict__ bo_g,
    float* __restrict__ out)
{
    extern __shared__ char smem[];
    uint2* sG    = (uint2*)smem;                    // 4096 uint2
    uint2* sVW   = (uint2*)(smem + 32768);          // 4096 uint2
    float* sbias = (float*)(smem + 65536);          // 256
    float* sbo   = (float*)(smem + 66560);          // 64

    int t = threadIdx.x, lane = t & 31, w = t >> 5;
    int lq = lane >> 2, lr = lane & 3;
    int m0 = w * 16;
    int b  = blockIdx.y;
    int n0 = blockIdx.x * 128;

    // ---- A-fragments of X from global, fp16 (k=64 -> 4 ksteps) ----
    uint32_t afr[4][4];
    {
        const float* x0 = inp + ((size_t)(b * NQ + n0 + m0 + lq)) * 64;
        const float* x1 = x0 + 8 * 64;
#pragma unroll
        for (int ks = 0; ks < 4; ++ks) {
            float2 u0 = *(const float2*)&x0[ks * 16 + 2 * lr];
            float2 u1 = *(const float2*)&x1[ks * 16 + 2 * lr];
            float2 u2 = *(const float2*)&x0[ks * 16 + 8 + 2 * lr];
            float2 u3 = *(const float2*)&x1[ks * 16 + 8 + 2 * lr];
            afr[ks][0] = pack_h2(u0.x, u0.y);
            afr[ks][1] = pack_h2(u1.x, u1.y);
            afr[ks][2] = pack_h2(u2.x, u2.y);
            afr[ks][3] = pack_h2(u3.x, u3.y);
        }
    }

    // ---- stage fragment blobs (linear copies) ----
    {
        const uint4* gG = (const uint4*)g_Gh + b * 2048;
        const uint4* gV = (const uint4*)g_VWh + b * 2048;
#pragma unroll
        for (int it = 0; it < 8; ++it) {
            ((uint4*)sG)[it * 256 + t]  = gG[it * 256 + t];
            ((uint4*)sVW)[it * 256 + t] = gV[it * 256 + t];
        }
    }
    if (t < 64) ((float4*)sbias)[t] = ((const float4*)(g_sbias + (b << 8)))[t];
    if (t < 16) ((float4*)sbo)[t]   = ((const float4*)bo_g)[t];
    __syncthreads();

    // ---- GEMM1: S = X @ G^T, 128 mma + 128 LDS.64 per warp ----
    float acc[32][4];
#pragma unroll
    for (int nt = 0; nt < 32; ++nt)
#pragma unroll
        for (int i = 0; i < 4; ++i) acc[nt][i] = 0.0f;

#pragma unroll
    for (int ks = 0; ks < 4; ++ks) {
#pragma unroll
        for (int nt = 0; nt < 32; ++nt) {
            uint2 bb = sG[(nt * 4 + ks) * 32 + lane];
            mma_f16(acc[nt], afr[ks], bb.x, bb.y);
        }
    }

    // ---- softmax in regs: +bias, row max (quad), exp, row sums (quad) ----
    float mx0 = -1e30f, mx1 = -1e30f;
#pragma unroll
    for (int nt = 0; nt < 32; ++nt) {
        int c = nt * 8 + 2 * lr;
        float bi0 = sbias[c], bi1 = sbias[c + 1];
        acc[nt][0] += bi0; acc[nt][1] += bi1;
        acc[nt][2] += bi0; acc[nt][3] += bi1;
        mx0 = fmaxf(mx0, fmaxf(acc[nt][0], acc[nt][1]));
        mx1 = fmaxf(mx1, fmaxf(acc[nt][2], acc[nt][3]));
    }
    mx0 = fmaxf(mx0, __shfl_xor_sync(0xffffffffu, mx0, 1));
    mx0 = fmaxf(mx0, __shfl_xor_sync(0xffffffffu, mx0, 2));
    mx1 = fmaxf(mx1, __shfl_xor_sync(0xffffffffu, mx1, 1));
    mx1 = fmaxf(mx1, __shfl_xor_sync(0xffffffffu, mx1, 2));

    float sum0 = 0.0f, sum1 = 0.0f;
#pragma unroll
    for (int nt = 0; nt < 32; ++nt) {
        float e0 = __expf(acc[nt][0] - mx0);
        float e1 = __expf(acc[nt][1] - mx0);
        float e2 = __expf(acc[nt][2] - mx1);
        float e3 = __expf(acc[nt][3] - mx1);
        sum0 += e0 + e1;
        sum1 += e2 + e3;
        acc[nt][0] = e0; acc[nt][1] = e1;
        acc[nt][2] = e2; acc[nt][3] = e3;
    }
    sum0 += __shfl_xor_sync(0xffffffffu, sum0, 1);
    sum0 += __shfl_xor_sync(0xffffffffu, sum0, 2);
    sum1 += __shfl_xor_sync(0xffffffffu, sum1, 1);
    sum1 += __shfl_xor_sync(0xffffffffu, sum1, 2);
    float rv0 = 1.0f / sum0;
    float rv1 = 1.0f / sum1;

    // ---- GEMM2: O = P @ VW^T; A-frags = packed own C-frags (no shfl) ----
    float acc2[8][4];
#pragma unroll
    for (int ct = 0; ct < 8; ++ct)
#pragma unroll
        for (int i = 0; i < 4; ++i) acc2[ct][i] = 0.0f;

#pragma unroll
    for (int ks = 0; ks < 16; ++ks) {
        uint32_t pa[4];
        pa[0] = pack_h2(acc[2 * ks][0],     acc[2 * ks][1]);
        pa[1] = pack_h2(acc[2 * ks][2],     acc[2 * ks][3]);
        pa[2] = pack_h2(acc[2 * ks + 1][0], acc[2 * ks + 1][1]);
        pa[3] = pack_h2(acc[2 * ks + 1][2], acc[2 * ks + 1][3]);
#pragma unroll
        for (int ct = 0; ct < 8; ++ct) {
            uint2 bb = sVW[(ct * 16 + ks) * 32 + lane];
            mma_f16(acc2[ct], pa, bb.x, bb.y);
        }
    }

    // ---- epilogue ----
    {
        size_t rg = (size_t)(b * NQ + n0 + m0 + lq) * 64;
#pragma unroll
        for (int ct = 0; ct < 8; ++ct) {
            int c = ct * 8 + 2 * lr;
            float2 o0 = make_float2(acc2[ct][0] * rv0 + sbo[c],
                                    acc2[ct][1] * rv0 + sbo[c + 1]);
            float2 o1 = make_float2(acc2[ct][2] * rv1 + sbo[c],
                                    acc2[ct][3] * rv1 + sbo[c + 1]);
            *(float2*)&out[rg + c] = o0;
            *(float2*)&out[rg + 8 * 64 + c] = o1;
        }
    }
}

// ---------------------------------------------------------------------------
extern "C" void kernel_launch(void* const* d_in, const int* in_sizes, int n_in,
                              void* d_out, int out_size)
{
    const float* inp   = (const float*)d_in[0];
    const float* Wq    = (const float*)d_in[1];
    const float* bq    = (const float*)d_in[2];
    const float* Wkv   = (const float*)d_in[3];
    const float* bkv   = (const float*)d_in[4];
    const float* Wo    = (const float*)d_in[5];
    const float* bo    = (const float*)d_in[6];
    const float* convw = (const float*)d_in[7];
    const float* convb = (const float*)d_in[8];
    const float* gamma = (const float*)d_in[9];
    const float* beta  = (const float*)d_in[10];
    float* out = (float*)d_out;

    const int smemB = 17026 * 4;
    cudaFuncSetAttribute(kv_kernel,   cudaFuncAttributeMaxDynamicSharedMemorySize, smemB);
    cudaFuncSetAttribute(attn_kernel, cudaFuncAttributeMaxDynamicSharedMemorySize, AT_SMEM);

    conv_kernel<<<128, 256>>>(inp, convw, convb);
    kv_kernel<<<512, 256, smemB>>>(Wq, bq, Wkv, bkv, Wo, gamma, beta);
    attn_kernel<<<dim3(128, 16), 256, AT_SMEM>>>(inp, bo, out);
}